// round 8
// baseline (speedup 1.0000x reference)
#include <cuda_runtime.h>
#include <cuda_bf16.h>
#include <cstdint>

#define B_ 16
#define N_ 1024
#define D_ 128

// ---------------------------------------------------------------------------
// Scratch (device globals — no allocation allowed)
// ---------------------------------------------------------------------------
__device__ float d_As[D_*D_];
__device__ float d_Wcat[D_*256];      // [WwT | W2]
__device__ float d_bcat[256];         // [Wb | Wb@As]
__device__ float d_csum[B_*N_];
__device__ uint32_t d_adjbit[B_*N_*32];   // 2 MB bitmask: word=(b*1024+p)*32+(q>>5)
__device__ __nv_bfloat16 d_gsH[B_*8*16384];
__device__ __nv_bfloat16 d_gsL[B_*8*16384];
__device__ __nv_bfloat16 d_hH [B_*8*16384];
__device__ __nv_bfloat16 d_hL [B_*8*16384];
__device__ __nv_bfloat16 d_numH[(size_t)B_*N_*N_];
__device__ __nv_bfloat16 d_numL[(size_t)B_*N_*N_];
__device__ __nv_bfloat16 d_hsTH[B_*8*16384];
__device__ __nv_bfloat16 d_hsTL[B_*8*16384];

// ---------------------------------------------------------------------------
// helpers (sm_80-era PTX only)
// ---------------------------------------------------------------------------
__device__ __forceinline__ uint32_t smem_to_u32(const void* p){
    uint32_t a;
    asm("{ .reg .u64 t; cvta.to.shared.u64 t, %1; cvt.u32.u64 %0, t; }" : "=r"(a) : "l"(p));
    return a;
}
__device__ __forceinline__ uint32_t hswz(int row, int kb){
    return (uint32_t)(row*128) + (uint32_t)(((((kb >> 4) ^ (row & 7)) & 7) << 4) | (kb & 15));
}
__device__ __forceinline__ void ldm4a(uint32_t addr, uint32_t r[4]){
    asm volatile("ldmatrix.sync.aligned.m8n8.x4.shared.b16 {%0,%1,%2,%3}, [%4];"
        : "=r"(r[0]), "=r"(r[1]), "=r"(r[2]), "=r"(r[3]) : "r"(addr));
}
__device__ __forceinline__ void mma16816(float* d, const uint32_t* a, uint32_t b0, uint32_t b1){
    asm volatile("mma.sync.aligned.m16n8k16.row.col.f32.bf16.bf16.f32 "
        "{%0,%1,%2,%3}, {%4,%5,%6,%7}, {%8,%9}, {%0,%1,%2,%3};"
        : "+f"(d[0]), "+f"(d[1]), "+f"(d[2]), "+f"(d[3])
        : "r"(a[0]), "r"(a[1]), "r"(a[2]), "r"(a[3]), "r"(b0), "r"(b1));
}
__device__ __forceinline__ void cpy(uint32_t sdst, const char* g, int tid, int n16){
    for (int i = tid; i < n16; i += 256){
        asm volatile("cp.async.cg.shared.global [%0], [%1], 16;"
            :: "r"(sdst + (uint32_t)i*16), "l"(g + (size_t)i*16));
    }
}
#define CP_COMMIT() asm volatile("cp.async.commit_group;" ::: "memory")
#define CP_WAIT(n)  asm volatile("cp.async.wait_group %0;" :: "n"(n) : "memory")

__device__ __forceinline__ void pack2(float a, float b, uint32_t& ph, uint32_t& pl){
    __nv_bfloat16 ah = __float2bfloat16(a), bh = __float2bfloat16(b);
    __nv_bfloat16 al = __float2bfloat16(a - __bfloat162float(ah));
    __nv_bfloat16 bl = __float2bfloat16(b - __bfloat162float(bh));
    ph = (uint32_t)__bfloat16_as_ushort(ah) | ((uint32_t)__bfloat16_as_ushort(bh) << 16);
    pl = (uint32_t)__bfloat16_as_ushort(al) | ((uint32_t)__bfloat16_as_ushort(bl) << 16);
}
__device__ __forceinline__ float fast_sigmoid(float z){
    return __fdividef(1.f, 1.f + __expf(-z));
}
__device__ __forceinline__ float fast_tanh(float z){
    float t = __expf(2.f*z);                 // inf for big z -> 1; 0 for small -> -1
    return 1.f - __fdividef(2.f, t + 1.f);
}

// ---------------------------------------------------------------------------
// prep
// ---------------------------------------------------------------------------
__global__ void k_prep(const float* __restrict__ Ww, const float* __restrict__ A){
    int idx = blockIdx.x*256 + threadIdx.x;
    int r = idx >> 7, c = idx & 127;
    d_As[r*D_ + c]      = A[r*D_ + c] + A[c*D_ + r];
    d_Wcat[c*256 + r]   = Ww[r*D_ + c];
    d_csum[idx] = 0.f;
}
__global__ void k_prep2(const float* __restrict__ Ww, const float* __restrict__ Wb){
    if (blockIdx.x == 64){
        int c = threadIdx.x;
        if (c < 128){
            float s = 0.f;
            for (int d = 0; d < 128; ++d) s = fmaf(Wb[d], d_As[d*D_ + c], s);
            d_bcat[c] = Wb[c];
            d_bcat[128 + c] = s;
        }
        return;
    }
    int idx = blockIdx.x*256 + threadIdx.x;
    int k = idx >> 7, c = idx & 127;
    float s = 0.f;
    for (int j = 0; j < 128; ++j) s = fmaf(Ww[j*D_ + k], d_As[j*D_ + c], s);
    d_Wcat[k*256 + 128 + c] = s;
}
// adj (0/1 floats, 64MB) -> bitmask (2MB). warp: 64 words = 2048 floats.
__global__ void k_adjbit(const float* __restrict__ adj){
    int w = blockIdx.x*8 + (threadIdx.x >> 5);
    int lane = threadIdx.x & 31;
    size_t base = (size_t)w*2048;
    uint32_t* dst = &d_adjbit[w*64];
    #pragma unroll 4
    for (int i = 0; i < 64; ++i){
        float v = adj[base + (size_t)i*32 + lane];
        uint32_t m = __ballot_sync(0xffffffffu, v > 0.f);
        if (lane == 0) dst[i] = m;
    }
}

// ---------------------------------------------------------------------------
// k_hg: [h | gs] = x @ Wcat + bcat  (fp32) -> 4 split tile images
// ---------------------------------------------------------------------------
__global__ void k_hg(const float* __restrict__ x){
    __shared__ float sA[32*32];
    __shared__ float sB[32*256];
    int tid = threadIdx.x, tx = tid & 31, ty = tid >> 5;
    int rowBase = blockIdx.x << 5;
    float acc[4][2][4] = {};
    for (int k0 = 0; k0 < D_; k0 += 32){
        { int r = tid >> 3, c4 = (tid & 7) << 2;
          *(float4*)&sA[r*32 + c4] = *(const float4*)&x[(size_t)(rowBase + r)*D_ + k0 + c4]; }
        #pragma unroll
        for (int it = 0; it < 8; ++it){
            int lin = (it << 8) + tid, r = lin >> 6, c4 = (lin & 63) << 2;
            *(float4*)&sB[r*256 + c4] = *(const float4*)&d_Wcat[(size_t)(k0 + r)*256 + c4];
        }
        __syncthreads();
        #pragma unroll
        for (int kk = 0; kk < 32; ++kk){
            float a0 = sA[(ty*4+0)*32+kk], a1 = sA[(ty*4+1)*32+kk];
            float a2 = sA[(ty*4+2)*32+kk], a3 = sA[(ty*4+3)*32+kk];
            float4 bh = *(float4*)&sB[kk*256 + (tx<<2)];
            float4 bg = *(float4*)&sB[kk*256 + 128 + (tx<<2)];
            acc[0][0][0]=fmaf(a0,bh.x,acc[0][0][0]); acc[0][0][1]=fmaf(a0,bh.y,acc[0][0][1]);
            acc[0][0][2]=fmaf(a0,bh.z,acc[0][0][2]); acc[0][0][3]=fmaf(a0,bh.w,acc[0][0][3]);
            acc[0][1][0]=fmaf(a0,bg.x,acc[0][1][0]); acc[0][1][1]=fmaf(a0,bg.y,acc[0][1][1]);
            acc[0][1][2]=fmaf(a0,bg.z,acc[0][1][2]); acc[0][1][3]=fmaf(a0,bg.w,acc[0][1][3]);
            acc[1][0][0]=fmaf(a1,bh.x,acc[1][0][0]); acc[1][0][1]=fmaf(a1,bh.y,acc[1][0][1]);
            acc[1][0][2]=fmaf(a1,bh.z,acc[1][0][2]); acc[1][0][3]=fmaf(a1,bh.w,acc[1][0][3]);
            acc[1][1][0]=fmaf(a1,bg.x,acc[1][1][0]); acc[1][1][1]=fmaf(a1,bg.y,acc[1][1][1]);
            acc[1][1][2]=fmaf(a1,bg.z,acc[1][1][2]); acc[1][1][3]=fmaf(a1,bg.w,acc[1][1][3]);
            acc[2][0][0]=fmaf(a2,bh.x,acc[2][0][0]); acc[2][0][1]=fmaf(a2,bh.y,acc[2][0][1]);
            acc[2][0][2]=fmaf(a2,bh.z,acc[2][0][2]); acc[2][0][3]=fmaf(a2,bh.w,acc[2][0][3]);
            acc[2][1][0]=fmaf(a2,bg.x,acc[2][1][0]); acc[2][1][1]=fmaf(a2,bg.y,acc[2][1][1]);
            acc[2][1][2]=fmaf(a2,bg.z,acc[2][1][2]); acc[2][1][3]=fmaf(a2,bg.w,acc[2][1][3]);
            acc[3][0][0]=fmaf(a3,bh.x,acc[3][0][0]); acc[3][0][1]=fmaf(a3,bh.y,acc[3][0][1]);
            acc[3][0][2]=fmaf(a3,bh.z,acc[3][0][2]); acc[3][0][3]=fmaf(a3,bh.w,acc[3][0][3]);
            acc[3][1][0]=fmaf(a3,bg.x,acc[3][1][0]); acc[3][1][1]=fmaf(a3,bg.y,acc[3][1][1]);
            acc[3][1][2]=fmaf(a3,bg.z,acc[3][1][2]); acc[3][1][3]=fmaf(a3,bg.w,acc[3][1][3]);
        }
        __syncthreads();
    }
    float4 bvh = *(const float4*)&d_bcat[tx<<2];
    float4 bvg = *(const float4*)&d_bcat[128 + (tx<<2)];
    int kb = tx*8, half = kb >> 7, kb2 = kb & 127;
    #pragma unroll
    for (int i = 0; i < 4; ++i){
        int row = rowBase + ty*4 + i;
        int b = row >> 10, ct = (row >> 7) & 7, rl = row & 127;
        size_t base = (size_t)(b*8 + ct)*32768 + (size_t)half*16384 + hswz(rl, kb2);
        float4 oh, og;
        oh.x=acc[i][0][0]+bvh.x; oh.y=acc[i][0][1]+bvh.y; oh.z=acc[i][0][2]+bvh.z; oh.w=acc[i][0][3]+bvh.w;
        og.x=acc[i][1][0]+bvg.x; og.y=acc[i][1][1]+bvg.y; og.z=acc[i][1][2]+bvg.z; og.w=acc[i][1][3]+bvg.w;
        uint32_t h0,l0,h1,l1;
        pack2(oh.x,oh.y,h0,l0); pack2(oh.z,oh.w,h1,l1);
        *(uint32_t*)((char*)d_hH + base)     = h0; *(uint32_t*)((char*)d_hL + base)     = l0;
        *(uint32_t*)((char*)d_hH + base + 4) = h1; *(uint32_t*)((char*)d_hL + base + 4) = l1;
        pack2(og.x,og.y,h0,l0); pack2(og.z,og.w,h1,l1);
        *(uint32_t*)((char*)d_gsH + base)     = h0; *(uint32_t*)((char*)d_gsL + base)     = l0;
        *(uint32_t*)((char*)d_gsH + base + 4) = h1; *(uint32_t*)((char*)d_gsL + base + 4) = l1;
    }
}

// ---------------------------------------------------------------------------
// k_hsT: hsT[d][q] = h[q][d]/csum[q]  (h from hi/lo images)
// ---------------------------------------------------------------------------
__global__ void k_hsT(){
    extern __shared__ float sT[];   // 128*129
    int qc = blockIdx.x, b = blockIdx.y, tid = threadIdx.x;
    size_t tileB = (size_t)(b*8 + qc)*32768;
    for (int g = tid; g < 2048; g += 256){
        int q = g >> 4, col8 = (g & 15) << 3;
        int kb = col8*2, half = kb >> 7, kb2 = kb & 127;
        size_t base = tileB + (size_t)half*16384 + hswz(q, kb2);
        uint4 uh = *(const uint4*)((const char*)d_hH + base);
        uint4 ul = *(const uint4*)((const char*)d_hL + base);
        float r = 1.0f / d_csum[b*N_ + qc*128 + q];
        const uint32_t wh[4] = {uh.x,uh.y,uh.z,uh.w};
        const uint32_t wl[4] = {ul.x,ul.y,ul.z,ul.w};
        #pragma unroll
        for (int t = 0; t < 4; ++t){
            float v0 = __bfloat162float(__ushort_as_bfloat16((unsigned short)(wh[t] & 0xffff)))
                     + __bfloat162float(__ushort_as_bfloat16((unsigned short)(wl[t] & 0xffff)));
            float v1 = __bfloat162float(__ushort_as_bfloat16((unsigned short)(wh[t] >> 16)))
                     + __bfloat162float(__ushort_as_bfloat16((unsigned short)(wl[t] >> 16)));
            sT[(col8 + 2*t)*129 + q]     = v0*r;
            sT[(col8 + 2*t + 1)*129 + q] = v1*r;
        }
    }
    __syncthreads();
    for (int g = tid; g < 2048; g += 256){
        int dd = g >> 4, q8 = (g & 15) << 3;
        int kb = q8*2, half = kb >> 7, kb2 = kb & 127;
        uint32_t h[4], l[4];
        #pragma unroll
        for (int i = 0; i < 4; ++i)
            pack2(sT[dd*129 + q8 + 2*i], sT[dd*129 + q8 + 2*i + 1], h[i], l[i]);
        size_t base = tileB + (size_t)half*16384 + hswz(dd, kb2);
        *(uint4*)((char*)d_hsTH + base) = make_uint4(h[0],h[1],h[2],h[3]);
        *(uint4*)((char*)d_hsTL + base) = make_uint4(l[0],l[1],l[2],l[3]);
    }
}

// ---------------------------------------------------------------------------
// stage layout: aH 0 | aL 8K | bH 16K | bL 32K (48KB); two stages = 96KB
// ---------------------------------------------------------------------------
#define ST_AL 8192
#define ST_BH 16384
#define ST_BL 32768
#define ST_SZ 49152
#define SMEM_BYTES (2*ST_SZ + 512 + 1024)

__device__ __forceinline__ void mma_half(uint32_t st, int m0w, int n0, float acc[2][4][4]){
    int lane = threadIdx.x & 31;
    int lrow = lane & 15;
    uint32_t lk = (uint32_t)((lane >> 4) << 4);
    uint32_t aHa[2], aLa[2], bHa[2], bLa[2];
    #pragma unroll
    for (int mt = 0; mt < 2; ++mt){
        uint32_t o = hswz(m0w + mt*16 + lrow, lk);
        aHa[mt] = st + o; aLa[mt] = st + ST_AL + o;
    }
    #pragma unroll
    for (int np = 0; np < 2; ++np){
        uint32_t o = hswz(n0 + np*16 + lrow, lk);
        bHa[np] = st + ST_BH + o; bLa[np] = st + ST_BL + o;
    }
    #pragma unroll
    for (int k4 = 0; k4 < 4; ++k4){
        uint32_t xo = (uint32_t)(k4 << 5);
        uint32_t aH[2][4], aL[2][4], bH[2][4], bL[2][4];
        #pragma unroll
        for (int mt = 0; mt < 2; ++mt){ ldm4a(aHa[mt]^xo, aH[mt]); ldm4a(aLa[mt]^xo, aL[mt]); }
        #pragma unroll
        for (int np = 0; np < 2; ++np){ ldm4a(bHa[np]^xo, bH[np]); ldm4a(bLa[np]^xo, bL[np]); }
        #pragma unroll
        for (int mt = 0; mt < 2; ++mt)
        #pragma unroll
        for (int np = 0; np < 2; ++np)
        #pragma unroll
        for (int hf = 0; hf < 2; ++hf){
            float* d = acc[mt][np*2 + hf];
            mma16816(d, aH[mt], bH[np][hf], bH[np][2 + hf]);
            mma16816(d, aH[mt], bL[np][hf], bL[np][2 + hf]);
            mma16816(d, aL[mt], bH[np][hf], bH[np][2 + hf]);
        }
    }
}

// ---------------------------------------------------------------------------
// kB: e = gs @ h^T; mask from smem bitmask; fused __expf/colsum epilogue;
// numer hi/lo -> tile images. grid (8,16,16)
// ---------------------------------------------------------------------------
__global__ void __launch_bounds__(256, 2) kB(){
    extern __shared__ char smem[];
    uint32_t sb = smem_to_u32(smem);
    int tid = threadIdx.x, lane = tid & 31, wid = tid >> 5;
    int qt = blockIdx.x, pth = blockIdx.y, b = blockIdx.z;
    int ptc = pth >> 1, mrow = pth & 1;
    int m0w = (wid >> 2)*32, n0 = (wid & 3)*32;

    size_t ga = (size_t)(b*8 + ptc)*32768 + (size_t)mrow*8192;
    size_t gb = (size_t)(b*8 + qt)*32768;

    cpy(sb,          (const char*)d_gsH + ga, tid, 512);
    cpy(sb + ST_AL,  (const char*)d_gsL + ga, tid, 512);
    cpy(sb + ST_BH,  (const char*)d_hH  + gb, tid, 1024);
    cpy(sb + ST_BL,  (const char*)d_hL  + gb, tid, 1024);
    // bit tile: 64 rows x 16B (4 words), rows p = pth*64 + r
    if (tid < 64){
        const char* gbit = (const char*)d_adjbit
            + ((size_t)(b*1024 + pth*64 + tid))*128 + (size_t)qt*16;
        asm volatile("cp.async.ca.shared.global [%0], [%1], 16;"
            :: "r"(sb + (uint32_t)(2*ST_SZ + 512 + tid*16)), "l"(gbit));
    }
    CP_COMMIT();

    float acc[2][4][4] = {};
    {
        uint32_t s1 = sb + ST_SZ;
        cpy(s1,         (const char*)d_gsH + ga + 16384, tid, 512);
        cpy(s1 + ST_AL, (const char*)d_gsL + ga + 16384, tid, 512);
        cpy(s1 + ST_BH, (const char*)d_hH  + gb + 16384, tid, 1024);
        cpy(s1 + ST_BL, (const char*)d_hL  + gb + 16384, tid, 1024);
        CP_COMMIT();
        CP_WAIT(1);
        __syncthreads();
        mma_half(sb, m0w, n0, acc);
        CP_WAIT(0);
        __syncthreads();
        mma_half(sb + ST_SZ, m0w, n0, acc);
        __syncthreads();
    }

    float* scol = (float*)(smem + 2*ST_SZ);
    const uint32_t* sBits = (const uint32_t*)(smem + 2*ST_SZ + 512);
    if (tid < 128) scol[tid] = 0.f;
    __syncthreads();

    char* stH = smem;
    char* stL = smem + 16384;
    float cs[8] = {};
    #pragma unroll
    for (int mt = 0; mt < 2; ++mt){
        int r1 = m0w + mt*16 + (lane >> 2);
        #pragma unroll
        for (int nt = 0; nt < 4; ++nt){
            int c0 = n0 + nt*8 + ((lane & 3) << 1);
            const float* d = acc[mt][nt];
            #pragma unroll
            for (int hf = 0; hf < 2; ++hf){
                int r = r1 + hf*8;
                uint32_t w = sBits[r*4 + (c0 >> 5)];
                bool a0 = (w >> (c0 & 31)) & 1u;
                bool a1 = (w >> ((c0 & 31) + 1)) & 1u;
                float e0 = d[hf*2 + 0], e1 = d[hf*2 + 1];
                float ev0 = a0 ? __expf(e0) : 1.f;
                float ev1 = a1 ? __expf(e1) : 1.f;
                float nv0 = a0 ? ev0 : 0.f;
                float nv1 = a1 ? ev1 : 0.f;
                cs[nt*2 + 0] += ev0; cs[nt*2 + 1] += ev1;
                uint32_t ph, pl; pack2(nv0, nv1, ph, pl);
                int kb = c0*2, half = kb >> 7;
                uint32_t off = (uint32_t)half*8192 + hswz(r, kb & 127);
                *(uint32_t*)(stH + off) = ph;
                *(uint32_t*)(stL + off) = pl;
            }
        }
    }
    #pragma unroll
    for (int m = 4; m < 32; m <<= 1){
        #pragma unroll
        for (int i = 0; i < 8; ++i) cs[i] += __shfl_xor_sync(0xffffffffu, cs[i], m);
    }
    if (lane < 4){
        #pragma unroll
        for (int nt = 0; nt < 4; ++nt){
            atomicAdd(&scol[n0 + nt*8 + 2*lane],     cs[nt*2]);
            atomicAdd(&scol[n0 + nt*8 + 2*lane + 1], cs[nt*2 + 1]);
        }
    }
    __syncthreads();
    if (tid < 128) atomicAdd(&d_csum[b*N_ + qt*128 + tid], scol[tid]);

    size_t tnum = (size_t)(b*64 + ptc*8 + qt)*32768 + (size_t)mrow*8192;
    #pragma unroll
    for (int half = 0; half < 2; ++half){
        uint4* gH = (uint4*)((char*)d_numH + tnum + (size_t)half*16384);
        uint4* gL = (uint4*)((char*)d_numL + tnum + (size_t)half*16384);
        const uint4* sH = (const uint4*)(stH + half*8192);
        const uint4* sL = (const uint4*)(stL + half*8192);
        for (int i = tid; i < 512; i += 256){ gH[i] = sH[i]; gL[i] = sL[i]; }
    }
}

// ---------------------------------------------------------------------------
// kC: h' = numer @ hsT^T, 16 pipelined K-half steps, fused gates epilogue.
// grid (8, 2, 16)
// ---------------------------------------------------------------------------
__global__ void __launch_bounds__(256, 2) kC(const float* __restrict__ x,
        const float* __restrict__ wiu, const float* __restrict__ wix,
        const float* __restrict__ wfu, const float* __restrict__ wfx,
        const float* __restrict__ wou, const float* __restrict__ wox,
        float* __restrict__ out){
    extern __shared__ char smem[];
    uint32_t sb = smem_to_u32(smem);
    int tid = threadIdx.x, lane = tid & 31, wid = tid >> 5;
    int pt = blockIdx.x, mh = blockIdx.y, b = blockIdx.z;
    int m0w = (wid >> 2)*32, n0 = (wid & 3)*32, wn = wid & 3;

    {
        size_t ta = (size_t)(b*64 + pt*8)*32768 + (size_t)mh*8192;
        size_t tb = (size_t)(b*8)*32768;
        cpy(sb,         (const char*)d_numH + ta, tid, 512);
        cpy(sb + ST_AL, (const char*)d_numL + ta, tid, 512);
        cpy(sb + ST_BH, (const char*)d_hsTH + tb, tid, 1024);
        cpy(sb + ST_BL, (const char*)d_hsTL + tb, tid, 1024);
        CP_COMMIT();
    }

    float acc[2][4][4] = {};
    for (int t = 0; t < 16; ++t){
        if (t < 15){
            int tn = t + 1, qc = tn >> 1, kh = tn & 1;
            uint32_t s = sb + (uint32_t)((tn & 1) ? ST_SZ : 0);
            size_t ta = (size_t)(b*64 + pt*8 + qc)*32768 + (size_t)kh*16384 + (size_t)mh*8192;
            size_t tb = (size_t)(b*8 + qc)*32768 + (size_t)kh*16384;
            cpy(s,         (const char*)d_numH + ta, tid, 512);
            cpy(s + ST_AL, (const char*)d_numL + ta, tid, 512);
            cpy(s + ST_BH, (const char*)d_hsTH + tb, tid, 1024);
            cpy(s + ST_BL, (const char*)d_hsTL + tb, tid, 1024);
            CP_COMMIT();
            CP_WAIT(1);
        } else {
            CP_WAIT(0);
        }
        __syncthreads();
        mma_half(sb + (uint32_t)((t & 1) ? ST_SZ : 0), m0w, n0, acc);
        __syncthreads();
    }

    float* sx    = (float*)smem;                 // [64][132]
    float* sw    = (float*)(smem + 33792);       // [6][128]
    float* sPart = (float*)(smem + 36864);       // [4 wn][3][64]
    float* sGate = (float*)(smem + 39936);       // [3][64]
    const float* xb = x + ((size_t)b*N_ + pt*128 + mh*64)*D_;
    for (int g = tid; g < 2048; g += 256){
        int row = g >> 5, c4 = (g & 31) << 2;
        float4 v = *(const float4*)&xb[(size_t)row*D_ + c4];
        float* p = &sx[row*132 + c4];
        p[0]=v.x; p[1]=v.y; p[2]=v.z; p[3]=v.w;
    }
    if (tid < 128){
        sw[tid]       = wiu[tid]; sw[128 + tid] = wfu[tid]; sw[256 + tid] = wou[tid];
        sw[384 + tid] = wix[tid]; sw[512 + tid] = wfx[tid]; sw[640 + tid] = wox[tid];
    }
    __syncthreads();

    float pi[4] = {}, pf[4] = {}, po[4] = {};
    #pragma unroll
    for (int mt = 0; mt < 2; ++mt){
        #pragma unroll
        for (int nt = 0; nt < 4; ++nt){
            int c0 = n0 + nt*8 + ((lane & 3) << 1);
            float wi0 = sw[c0], wi1 = sw[c0+1];
            float wf0 = sw[128+c0], wf1 = sw[129+c0];
            float wo0 = sw[256+c0], wo1 = sw[257+c0];
            const float* d = acc[mt][nt];
            #pragma unroll
            for (int hf = 0; hf < 2; ++hf){
                float h0 = fmaxf(d[hf*2], 0.f), h1 = fmaxf(d[hf*2+1], 0.f);
                pi[mt*2+hf] += h0*wi0 + h1*wi1;
                pf[mt*2+hf] += h0*wf0 + h1*wf1;
                po[mt*2+hf] += h0*wo0 + h1*wo1;
            }
        }
    }
    #pragma unroll
    for (int m = 1; m < 4; m <<= 1){
        #pragma unroll
        for (int i = 0; i < 4; ++i){
            pi[i] += __shfl_xor_sync(0xffffffffu, pi[i], m);
            pf[i] += __shfl_xor_sync(0xffffffffu, pf[i], m);
            po[i] += __shfl_xor_sync(0xffffffffu, po[i], m);
        }
    }
    if ((lane & 3) == 0){
        #pragma unroll
        for (int mt = 0; mt < 2; ++mt)
        #pragma unroll
        for (int hf = 0; hf < 2; ++hf){
            int rl = m0w + mt*16 + (lane >> 2) + hf*8;
            sPart[(wn*3 + 0)*64 + rl] = pi[mt*2+hf];
            sPart[(wn*3 + 1)*64 + rl] = pf[mt*2+hf];
            sPart[(wn*3 + 2)*64 + rl] = po[mt*2+hf];
        }
    }
    __syncthreads();
    if (tid < 64){
        int r = tid;
        float si = 0.f, sf = 0.f, so = 0.f;
        #pragma unroll
        for (int w = 0; w < 4; ++w){
            si += sPart[(w*3 + 0)*64 + r];
            sf += sPart[(w*3 + 1)*64 + r];
            so += sPart[(w*3 + 2)*64 + r];
        }
        const float* srow = &sx[r*132];
        #pragma unroll 8
        for (int c = 0; c < 128; ++c){
            float xv = srow[c];
            si = fmaf(xv, sw[384 + c], si);
            sf = fmaf(xv, sw[512 + c], sf);
            so = fmaf(xv, sw[640 + c], so);
        }
        sGate[r]        = fast_sigmoid(si);
        sGate[64 + r]   = fast_sigmoid(sf);
        sGate[128 + r]  = fast_sigmoid(so);
    }
    __syncthreads();

    float* outb = out + ((size_t)b*N_ + pt*128 + mh*64)*D_;
    #pragma unroll
    for (int mt = 0; mt < 2; ++mt){
        #pragma unroll
        for (int nt = 0; nt < 4; ++nt){
            int c0 = n0 + nt*8 + ((lane & 3) << 1);
            const float* d = acc[mt][nt];
            #pragma unroll
            for (int hf = 0; hf < 2; ++hf){
                int rl = m0w + mt*16 + (lane >> 2) + hf*8;
                float ic = sGate[rl], fc = sGate[64 + rl], oc = sGate[128 + rl];
                float x0 = sx[rl*132 + c0], x1 = sx[rl*132 + c0 + 1];
                float h0 = fmaxf(d[hf*2], 0.f), h1 = fmaxf(d[hf*2+1], 0.f);
                float2 o;
                o.x = oc * fast_tanh(fmaf(ic, h0, fc*x0));
                o.y = oc * fast_tanh(fmaf(ic, h1, fc*x1));
                *(float2*)&outb[(size_t)rl*D_ + c0] = o;
            }
        }
    }
}

// ---------------------------------------------------------------------------
extern "C" void kernel_launch(void* const* d_in, const int* in_sizes, int n_in,
                              void* d_out, int out_size){
    const float* x   = (const float*)d_in[0];
    const float* adj = (const float*)d_in[1];
    const float* Ww  = (const float*)d_in[2];
    const float* Wb  = (const float*)d_in[3];
    const float* A   = (const float*)d_in[4];
    const float* wiu = (const float*)d_in[5];
    const float* wix = (const float*)d_in[6];
    const float* wfu = (const float*)d_in[7];
    const float* wfx = (const float*)d_in[8];
    const float* wou = (const float*)d_in[9];
    const float* wox = (const float*)d_in[10];
    float* out = (float*)d_out;

    cudaFuncSetAttribute(kB, cudaFuncAttributeMaxDynamicSharedMemorySize, SMEM_BYTES);
    cudaFuncSetAttribute(kC, cudaFuncAttributeMaxDynamicSharedMemorySize, SMEM_BYTES);
    cudaFuncSetAttribute(k_hsT, cudaFuncAttributeMaxDynamicSharedMemorySize, 128*129*4);

    k_adjbit<<<1024, 256>>>(adj);
    k_prep<<<64, 256>>>(Ww, A);
    k_prep2<<<65, 256>>>(Ww, Wb);
    k_hg<<<512, 256>>>(x);
    kB<<<dim3(8, 16, B_), 256, SMEM_BYTES>>>();
    k_hsT<<<dim3(8, B_), 256, 128*129*4>>>();
    kC<<<dim3(8, 2, B_), 256, SMEM_BYTES>>>(x, wiu, wix, wfu, wfx, wou, wox, out);
}

// round 9
// speedup vs baseline: 1.1676x; 1.1676x over previous
#include <cuda_runtime.h>
#include <cuda_bf16.h>
#include <cstdint>

#define B_ 16
#define N_ 1024
#define D_ 128

// ---------------------------------------------------------------------------
// Scratch (device globals — no allocation allowed)
// Tile images: per 128x128 bf16 tile, 2 K-halves x 16KB, 128B swizzled rows.
// ---------------------------------------------------------------------------
__device__ float d_As[D_*D_];
__device__ float d_Wcat[D_*256];      // [WwT | W2] row k -> 256 cols
__device__ float d_bcat[256];         // [Wb | Wb@As]
__device__ float d_csum[B_*N_];
__device__ __nv_bfloat16 d_xH [B_*8*16384];
__device__ __nv_bfloat16 d_xL [B_*8*16384];
__device__ __nv_bfloat16 d_WcH[2*16384];
__device__ __nv_bfloat16 d_WcL[2*16384];
__device__ __nv_bfloat16 d_gsH[B_*8*16384];
__device__ __nv_bfloat16 d_gsL[B_*8*16384];
__device__ __nv_bfloat16 d_hH [B_*8*16384];
__device__ __nv_bfloat16 d_hL [B_*8*16384];
__device__ __nv_bfloat16 d_numH[(size_t)B_*N_*N_];
__device__ __nv_bfloat16 d_numL[(size_t)B_*N_*N_];
__device__ __nv_bfloat16 d_hsTH[B_*8*16384];
__device__ __nv_bfloat16 d_hsTL[B_*8*16384];

// ---------------------------------------------------------------------------
// helpers (sm_80-era PTX only)
// ---------------------------------------------------------------------------
__device__ __forceinline__ uint32_t smem_to_u32(const void* p){
    uint32_t a;
    asm("{ .reg .u64 t; cvta.to.shared.u64 t, %1; cvt.u32.u64 %0, t; }" : "=r"(a) : "l"(p));
    return a;
}
__device__ __forceinline__ uint32_t hswz(int row, int kb){
    return (uint32_t)(row*128) + (uint32_t)(((((kb >> 4) ^ (row & 7)) & 7) << 4) | (kb & 15));
}
__device__ __forceinline__ void ldm4a(uint32_t addr, uint32_t r[4]){
    asm volatile("ldmatrix.sync.aligned.m8n8.x4.shared.b16 {%0,%1,%2,%3}, [%4];"
        : "=r"(r[0]), "=r"(r[1]), "=r"(r[2]), "=r"(r[3]) : "r"(addr));
}
__device__ __forceinline__ void mma16816(float* d, const uint32_t* a, uint32_t b0, uint32_t b1){
    asm volatile("mma.sync.aligned.m16n8k16.row.col.f32.bf16.bf16.f32 "
        "{%0,%1,%2,%3}, {%4,%5,%6,%7}, {%8,%9}, {%0,%1,%2,%3};"
        : "+f"(d[0]), "+f"(d[1]), "+f"(d[2]), "+f"(d[3])
        : "r"(a[0]), "r"(a[1]), "r"(a[2]), "r"(a[3]), "r"(b0), "r"(b1));
}
__device__ __forceinline__ void cpy(uint32_t sdst, const char* g, int tid, int n16){
    for (int i = tid; i < n16; i += 256){
        asm volatile("cp.async.cg.shared.global [%0], [%1], 16;"
            :: "r"(sdst + (uint32_t)i*16), "l"(g + (size_t)i*16));
    }
}
#define CP_COMMIT() asm volatile("cp.async.commit_group;" ::: "memory")
#define CP_WAIT(n)  asm volatile("cp.async.wait_group %0;" :: "n"(n) : "memory")

__device__ __forceinline__ void pack2(float a, float b, uint32_t& ph, uint32_t& pl){
    __nv_bfloat16 ah = __float2bfloat16(a), bh = __float2bfloat16(b);
    __nv_bfloat16 al = __float2bfloat16(a - __bfloat162float(ah));
    __nv_bfloat16 bl = __float2bfloat16(b - __bfloat162float(bh));
    ph = (uint32_t)__bfloat16_as_ushort(ah) | ((uint32_t)__bfloat16_as_ushort(bh) << 16);
    pl = (uint32_t)__bfloat16_as_ushort(al) | ((uint32_t)__bfloat16_as_ushort(bl) << 16);
}
__device__ __forceinline__ float fast_sigmoid(float z){
    return __fdividef(1.f, 1.f + __expf(-z));
}
__device__ __forceinline__ float fast_tanh(float z){
    float t = __expf(2.f*z);
    return 1.f - __fdividef(2.f, t + 1.f);
}

// ---------------------------------------------------------------------------
// prep
// ---------------------------------------------------------------------------
__global__ void k_prep(const float* __restrict__ Ww, const float* __restrict__ A){
    int idx = blockIdx.x*256 + threadIdx.x;
    int r = idx >> 7, c = idx & 127;
    d_As[r*D_ + c]      = A[r*D_ + c] + A[c*D_ + r];
    d_Wcat[c*256 + r]   = Ww[r*D_ + c];
    d_csum[idx] = 0.f;
}
__global__ void k_prep2(const float* __restrict__ Ww, const float* __restrict__ Wb){
    if (blockIdx.x == 64){
        int c = threadIdx.x;
        if (c < 128){
            float s = 0.f;
            for (int d = 0; d < 128; ++d) s = fmaf(Wb[d], d_As[d*D_ + c], s);
            d_bcat[c] = Wb[c];
            d_bcat[128 + c] = s;
        }
        return;
    }
    int idx = blockIdx.x*256 + threadIdx.x;
    int k = idx >> 7, c = idx & 127;
    float s = 0.f;
    for (int j = 0; j < 128; ++j) s = fmaf(Ww[j*D_ + k], d_As[j*D_ + c], s);
    d_Wcat[k*256 + 128 + c] = s;
}
// weight B-operand split: B[bt][n][k] = Wcat[k][bt*128+n] -> hi/lo images
__global__ void k_wsplit(){
    int g = blockIdx.x*256 + threadIdx.x;        // 4096 items
    int bt = g >> 11, rem = g & 2047;
    int n = rem >> 4, k8 = (rem & 15) << 3;
    float v[8];
    #pragma unroll
    for (int i = 0; i < 8; ++i) v[i] = d_Wcat[(size_t)(k8 + i)*256 + bt*128 + n];
    uint32_t h[4], l[4];
    #pragma unroll
    for (int i = 0; i < 4; ++i) pack2(v[2*i], v[2*i+1], h[i], l[i]);
    int kb = k8*2, half = kb >> 7;
    size_t base = (size_t)bt*32768 + (size_t)half*16384 + hswz(n, kb & 127);
    *(uint4*)((char*)d_WcH + base) = make_uint4(h[0],h[1],h[2],h[3]);
    *(uint4*)((char*)d_WcL + base) = make_uint4(l[0],l[1],l[2],l[3]);
}
// x -> hi/lo swizzled tile images
__global__ void k_xsplit(const float* __restrict__ x){
    int g = blockIdx.x*256 + threadIdx.x;        // 262144 items
    int tile = g >> 11, rem = g & 2047;
    int row = rem >> 4, c8 = (rem & 15) << 3;
    const float* sp = &x[((size_t)tile*128 + row)*D_ + c8];
    float v[8];
    *(float4*)v = *(const float4*)sp; *(float4*)(v+4) = *(const float4*)(sp+4);
    uint32_t h[4], l[4];
    #pragma unroll
    for (int i = 0; i < 4; ++i) pack2(v[2*i], v[2*i+1], h[i], l[i]);
    int kb = c8*2, half = kb >> 7;
    size_t base = (size_t)tile*32768 + (size_t)half*16384 + hswz(row, kb & 127);
    *(uint4*)((char*)d_xH + base) = make_uint4(h[0],h[1],h[2],h[3]);
    *(uint4*)((char*)d_xL + base) = make_uint4(l[0],l[1],l[2],l[3]);
}

// ---------------------------------------------------------------------------
// 3-term split MMA over one K-half; A image (aH@aB, aL@aB+8K, 64 rows),
// B image (bH@bB, bL@bB+16K, 128 rows). warp grid 2m x 4n, acc[2][4][4].
// ---------------------------------------------------------------------------
__device__ __forceinline__ void mma_half2(uint32_t aB, uint32_t bB,
                                          int m0w, int n0, float acc[2][4][4]){
    int lane = threadIdx.x & 31;
    int lrow = lane & 15;
    uint32_t lk = (uint32_t)((lane >> 4) << 4);
    uint32_t aHa[2], aLa[2], bHa[2], bLa[2];
    #pragma unroll
    for (int mt = 0; mt < 2; ++mt){
        uint32_t o = hswz(m0w + mt*16 + lrow, lk);
        aHa[mt] = aB + o; aLa[mt] = aB + 8192 + o;
    }
    #pragma unroll
    for (int np = 0; np < 2; ++np){
        uint32_t o = hswz(n0 + np*16 + lrow, lk);
        bHa[np] = bB + o; bLa[np] = bB + 16384 + o;
    }
    #pragma unroll
    for (int k4 = 0; k4 < 4; ++k4){
        uint32_t xo = (uint32_t)(k4 << 5);
        uint32_t aH[2][4], aL[2][4], bH[2][4], bL[2][4];
        #pragma unroll
        for (int mt = 0; mt < 2; ++mt){ ldm4a(aHa[mt]^xo, aH[mt]); ldm4a(aLa[mt]^xo, aL[mt]); }
        #pragma unroll
        for (int np = 0; np < 2; ++np){ ldm4a(bHa[np]^xo, bH[np]); ldm4a(bLa[np]^xo, bL[np]); }
        #pragma unroll
        for (int mt = 0; mt < 2; ++mt)
        #pragma unroll
        for (int np = 0; np < 2; ++np)
        #pragma unroll
        for (int hf = 0; hf < 2; ++hf){
            float* d = acc[mt][np*2 + hf];
            mma16816(d, aH[mt], bH[np][hf], bH[np][2 + hf]);
            mma16816(d, aH[mt], bL[np][hf], bL[np][2 + hf]);
            mma16816(d, aL[mt], bH[np][hf], bH[np][2 + hf]);
        }
    }
}

// ---------------------------------------------------------------------------
// k_hg_mma: [h | gs] = x @ [Ww^T | W2] + bcat via split HMMA.
// grid 256 CTAs (64 rows each). smem: A 32KB | B 32KB (reused as stage).
// ---------------------------------------------------------------------------
#define HG_B 32768
#define HG_SMEM 65536

__global__ void __launch_bounds__(256, 2) k_hg_mma(){
    extern __shared__ char smem[];
    uint32_t sb = smem_to_u32(smem);
    int tid = threadIdx.x, lane = tid & 31, wid = tid >> 5;
    int tile = blockIdx.x >> 1, mrow = blockIdx.x & 1;
    int m0w = (wid >> 2)*32, n0 = (wid & 3)*32;

    size_t gax = (size_t)tile*32768 + (size_t)mrow*8192;
    cpy(sb,         (const char*)d_xH + gax,         tid, 512);
    cpy(sb + 8192,  (const char*)d_xL + gax,         tid, 512);
    cpy(sb + 16384, (const char*)d_xH + gax + 16384, tid, 512);
    cpy(sb + 24576, (const char*)d_xL + gax + 16384, tid, 512);
    CP_COMMIT();

    for (int bt = 0; bt < 2; ++bt){
        float acc[2][4][4] = {};
        for (int half = 0; half < 2; ++half){
            size_t gw = (size_t)bt*32768 + (size_t)half*16384;
            cpy(sb + HG_B,         (const char*)d_WcH + gw, tid, 1024);
            cpy(sb + HG_B + 16384, (const char*)d_WcL + gw, tid, 1024);
            CP_COMMIT();
            CP_WAIT(0);
            __syncthreads();
            mma_half2(sb + (uint32_t)half*16384, sb + HG_B, m0w, n0, acc);
            __syncthreads();
        }
        // stage epilogue into B buffer
        char* stH = smem + HG_B;
        char* stL = smem + HG_B + 16384;
        #pragma unroll
        for (int mt = 0; mt < 2; ++mt){
            int r1 = m0w + mt*16 + (lane >> 2);
            #pragma unroll
            for (int nt = 0; nt < 4; ++nt){
                int c0 = n0 + nt*8 + ((lane & 3) << 1);
                float b0 = d_bcat[bt*128 + c0], b1 = d_bcat[bt*128 + c0 + 1];
                const float* d = acc[mt][nt];
                #pragma unroll
                for (int hf = 0; hf < 2; ++hf){
                    int r = r1 + hf*8;
                    uint32_t ph, pl; pack2(d[hf*2] + b0, d[hf*2+1] + b1, ph, pl);
                    int kb = c0*2, half = kb >> 7;
                    uint32_t off = (uint32_t)half*8192 + hswz(r, kb & 127);
                    *(uint32_t*)(stH + off) = ph;
                    *(uint32_t*)(stL + off) = pl;
                }
            }
        }
        __syncthreads();
        char* gH = (char*)(bt ? d_gsH : d_hH);
        char* gL = (char*)(bt ? d_gsL : d_hL);
        #pragma unroll
        for (int half = 0; half < 2; ++half){
            size_t gb = (size_t)tile*32768 + (size_t)half*16384 + (size_t)mrow*8192;
            uint4* dH = (uint4*)(gH + gb); uint4* dL = (uint4*)(gL + gb);
            const uint4* sH = (const uint4*)(stH + half*8192);
            const uint4* sL = (const uint4*)(stL + half*8192);
            for (int i = tid; i < 512; i += 256){ dH[i] = sH[i]; dL[i] = sL[i]; }
        }
        __syncthreads();
    }
}

// ---------------------------------------------------------------------------
// k_hsT: hsT[d][q] = h[q][d]/csum[q]  (h from hi/lo images)
// ---------------------------------------------------------------------------
__global__ void k_hsT(){
    extern __shared__ float sT[];   // 128*129
    int qc = blockIdx.x, b = blockIdx.y, tid = threadIdx.x;
    size_t tileB = (size_t)(b*8 + qc)*32768;
    for (int g = tid; g < 2048; g += 256){
        int q = g >> 4, col8 = (g & 15) << 3;
        int kb = col8*2, half = kb >> 7, kb2 = kb & 127;
        size_t base = tileB + (size_t)half*16384 + hswz(q, kb2);
        uint4 uh = *(const uint4*)((const char*)d_hH + base);
        uint4 ul = *(const uint4*)((const char*)d_hL + base);
        float r = 1.0f / d_csum[b*N_ + qc*128 + q];
        const uint32_t wh[4] = {uh.x,uh.y,uh.z,uh.w};
        const uint32_t wl[4] = {ul.x,ul.y,ul.z,ul.w};
        #pragma unroll
        for (int t = 0; t < 4; ++t){
            float v0 = __bfloat162float(__ushort_as_bfloat16((unsigned short)(wh[t] & 0xffff)))
                     + __bfloat162float(__ushort_as_bfloat16((unsigned short)(wl[t] & 0xffff)));
            float v1 = __bfloat162float(__ushort_as_bfloat16((unsigned short)(wh[t] >> 16)))
                     + __bfloat162float(__ushort_as_bfloat16((unsigned short)(wl[t] >> 16)));
            sT[(col8 + 2*t)*129 + q]     = v0*r;
            sT[(col8 + 2*t + 1)*129 + q] = v1*r;
        }
    }
    __syncthreads();
    for (int g = tid; g < 2048; g += 256){
        int dd = g >> 4, q8 = (g & 15) << 3;
        int kb = q8*2, half = kb >> 7, kb2 = kb & 127;
        uint32_t h[4], l[4];
        #pragma unroll
        for (int i = 0; i < 4; ++i)
            pack2(sT[dd*129 + q8 + 2*i], sT[dd*129 + q8 + 2*i + 1], h[i], l[i]);
        size_t base = tileB + (size_t)half*16384 + hswz(dd, kb2);
        *(uint4*)((char*)d_hsTH + base) = make_uint4(h[0],h[1],h[2],h[3]);
        *(uint4*)((char*)d_hsTL + base) = make_uint4(l[0],l[1],l[2],l[3]);
    }
}

// ---------------------------------------------------------------------------
// stage layout: aH 0 | aL 8K | bH 16K | bL 32K (48KB); two stages = 96KB
// ---------------------------------------------------------------------------
#define ST_AL 8192
#define ST_BH 16384
#define ST_BL 32768
#define ST_SZ 49152
#define SMEM_BYTES (2*ST_SZ + 512)

// ---------------------------------------------------------------------------
// kB: e = gs @ h^T; fused mask/__expf/colsum epilogue (adj direct loads);
// numer hi/lo -> tile images. grid (8,16,16)
// ---------------------------------------------------------------------------
__global__ void __launch_bounds__(256, 2) kB(const float* __restrict__ adj){
    extern __shared__ char smem[];
    uint32_t sb = smem_to_u32(smem);
    int tid = threadIdx.x, lane = tid & 31, wid = tid >> 5;
    int qt = blockIdx.x, pth = blockIdx.y, b = blockIdx.z;
    int ptc = pth >> 1, mrow = pth & 1;
    int m0w = (wid >> 2)*32, n0 = (wid & 3)*32;

    size_t ga = (size_t)(b*8 + ptc)*32768 + (size_t)mrow*8192;
    size_t gb = (size_t)(b*8 + qt)*32768;

    cpy(sb,          (const char*)d_gsH + ga, tid, 512);
    cpy(sb + ST_AL,  (const char*)d_gsL + ga, tid, 512);
    cpy(sb + ST_BH,  (const char*)d_hH  + gb, tid, 1024);
    cpy(sb + ST_BL,  (const char*)d_hL  + gb, tid, 1024);
    CP_COMMIT();

    float acc[2][4][4] = {};
    {
        uint32_t s1 = sb + ST_SZ;
        cpy(s1,         (const char*)d_gsH + ga + 16384, tid, 512);
        cpy(s1 + ST_AL, (const char*)d_gsL + ga + 16384, tid, 512);
        cpy(s1 + ST_BH, (const char*)d_hH  + gb + 16384, tid, 1024);
        cpy(s1 + ST_BL, (const char*)d_hL  + gb + 16384, tid, 1024);
        CP_COMMIT();
        CP_WAIT(1);
        __syncthreads();
        mma_half2(sb, sb + ST_BH, m0w, n0, acc);
        CP_WAIT(0);
        __syncthreads();
        mma_half2(sb + ST_SZ, sb + ST_SZ + ST_BH, m0w, n0, acc);
        __syncthreads();
    }

    float* scol = (float*)(smem + 2*ST_SZ);
    if (tid < 128) scol[tid] = 0.f;
    __syncthreads();

    const float* adjb = adj + (size_t)b*N_*N_ + (size_t)(pth*64)*N_ + qt*128;
    char* stH = smem;
    char* stL = smem + 16384;
    float cs[8] = {};
    #pragma unroll
    for (int mt = 0; mt < 2; ++mt){
        int r1 = m0w + mt*16 + (lane >> 2);
        #pragma unroll
        for (int nt = 0; nt < 4; ++nt){
            int c0 = n0 + nt*8 + ((lane & 3) << 1);
            const float* d = acc[mt][nt];
            #pragma unroll
            for (int hf = 0; hf < 2; ++hf){
                int r = r1 + hf*8;
                float2 av = *(const float2*)&adjb[(size_t)r*N_ + c0];
                float e0 = d[hf*2 + 0], e1 = d[hf*2 + 1];
                float ev0 = (av.x > 0.f) ? __expf(e0) : 1.f;
                float ev1 = (av.y > 0.f) ? __expf(e1) : 1.f;
                float nv0 = (av.x > 0.f) ? ev0 : 0.f;
                float nv1 = (av.y > 0.f) ? ev1 : 0.f;
                cs[nt*2 + 0] += ev0; cs[nt*2 + 1] += ev1;
                uint32_t ph, pl; pack2(nv0, nv1, ph, pl);
                int kb = c0*2, half = kb >> 7;
                uint32_t off = (uint32_t)half*8192 + hswz(r, kb & 127);
                *(uint32_t*)(stH + off) = ph;
                *(uint32_t*)(stL + off) = pl;
            }
        }
    }
    #pragma unroll
    for (int m = 4; m < 32; m <<= 1){
        #pragma unroll
        for (int i = 0; i < 8; ++i) cs[i] += __shfl_xor_sync(0xffffffffu, cs[i], m);
    }
    if (lane < 4){
        #pragma unroll
        for (int nt = 0; nt < 4; ++nt){
            atomicAdd(&scol[n0 + nt*8 + 2*lane],     cs[nt*2]);
            atomicAdd(&scol[n0 + nt*8 + 2*lane + 1], cs[nt*2 + 1]);
        }
    }
    __syncthreads();
    if (tid < 128) atomicAdd(&d_csum[b*N_ + qt*128 + tid], scol[tid]);

    size_t tnum = (size_t)(b*64 + ptc*8 + qt)*32768 + (size_t)mrow*8192;
    #pragma unroll
    for (int half = 0; half < 2; ++half){
        uint4* gH = (uint4*)((char*)d_numH + tnum + (size_t)half*16384);
        uint4* gL = (uint4*)((char*)d_numL + tnum + (size_t)half*16384);
        const uint4* sH = (const uint4*)(stH + half*8192);
        const uint4* sL = (const uint4*)(stL + half*8192);
        for (int i = tid; i < 512; i += 256){ gH[i] = sH[i]; gL[i] = sL[i]; }
    }
}

// ---------------------------------------------------------------------------
// kC: h' = numer @ hsT^T, 16 pipelined K-half steps, fused gates epilogue.
// grid (8, 2, 16)
// ---------------------------------------------------------------------------
__global__ void __launch_bounds__(256, 2) kC(const float* __restrict__ x,
        const float* __restrict__ wiu, const float* __restrict__ wix,
        const float* __restrict__ wfu, const float* __restrict__ wfx,
        const float* __restrict__ wou, const float* __restrict__ wox,
        float* __restrict__ out){
    extern __shared__ char smem[];
    uint32_t sb = smem_to_u32(smem);
    int tid = threadIdx.x, lane = tid & 31, wid = tid >> 5;
    int pt = blockIdx.x, mh = blockIdx.y, b = blockIdx.z;
    int m0w = (wid >> 2)*32, n0 = (wid & 3)*32, wn = wid & 3;

    {
        size_t ta = (size_t)(b*64 + pt*8)*32768 + (size_t)mh*8192;
        size_t tb = (size_t)(b*8)*32768;
        cpy(sb,         (const char*)d_numH + ta, tid, 512);
        cpy(sb + ST_AL, (const char*)d_numL + ta, tid, 512);
        cpy(sb + ST_BH, (const char*)d_hsTH + tb, tid, 1024);
        cpy(sb + ST_BL, (const char*)d_hsTL + tb, tid, 1024);
        CP_COMMIT();
    }

    float acc[2][4][4] = {};
    for (int t = 0; t < 16; ++t){
        if (t < 15){
            int tn = t + 1, qc = tn >> 1, kh = tn & 1;
            uint32_t s = sb + (uint32_t)((tn & 1) ? ST_SZ : 0);
            size_t ta = (size_t)(b*64 + pt*8 + qc)*32768 + (size_t)kh*16384 + (size_t)mh*8192;
            size_t tb = (size_t)(b*8 + qc)*32768 + (size_t)kh*16384;
            cpy(s,         (const char*)d_numH + ta, tid, 512);
            cpy(s + ST_AL, (const char*)d_numL + ta, tid, 512);
            cpy(s + ST_BH, (const char*)d_hsTH + tb, tid, 1024);
            cpy(s + ST_BL, (const char*)d_hsTL + tb, tid, 1024);
            CP_COMMIT();
            CP_WAIT(1);
        } else {
            CP_WAIT(0);
        }
        __syncthreads();
        uint32_t st = sb + (uint32_t)((t & 1) ? ST_SZ : 0);
        mma_half2(st, st + ST_BH, m0w, n0, acc);
        __syncthreads();
    }

    float* sx    = (float*)smem;                 // [64][132]
    float* sw    = (float*)(smem + 33792);       // [6][128]
    float* sPart = (float*)(smem + 36864);       // [4 wn][3][64]
    float* sGate = (float*)(smem + 39936);       // [3][64]
    const float* xb = x + ((size_t)b*N_ + pt*128 + mh*64)*D_;
    for (int g = tid; g < 2048; g += 256){
        int row = g >> 5, c4 = (g & 31) << 2;
        float4 v = *(const float4*)&xb[(size_t)row*D_ + c4];
        float* p = &sx[row*132 + c4];
        p[0]=v.x; p[1]=v.y; p[2]=v.z; p[3]=v.w;
    }
    if (tid < 128){
        sw[tid]       = wiu[tid]; sw[128 + tid] = wfu[tid]; sw[256 + tid] = wou[tid];
        sw[384 + tid] = wix[tid]; sw[512 + tid] = wfx[tid]; sw[640 + tid] = wox[tid];
    }
    __syncthreads();

    float pi[4] = {}, pf[4] = {}, po[4] = {};
    #pragma unroll
    for (int mt = 0; mt < 2; ++mt){
        #pragma unroll
        for (int nt = 0; nt < 4; ++nt){
            int c0 = n0 + nt*8 + ((lane & 3) << 1);
            float wi0 = sw[c0], wi1 = sw[c0+1];
            float wf0 = sw[128+c0], wf1 = sw[129+c0];
            float wo0 = sw[256+c0], wo1 = sw[257+c0];
            const float* d = acc[mt][nt];
            #pragma unroll
            for (int hf = 0; hf < 2; ++hf){
                float h0 = fmaxf(d[hf*2], 0.f), h1 = fmaxf(d[hf*2+1], 0.f);
                pi[mt*2+hf] += h0*wi0 + h1*wi1;
                pf[mt*2+hf] += h0*wf0 + h1*wf1;
                po[mt*2+hf] += h0*wo0 + h1*wo1;
            }
        }
    }
    #pragma unroll
    for (int m = 1; m < 4; m <<= 1){
        #pragma unroll
        for (int i = 0; i < 4; ++i){
            pi[i] += __shfl_xor_sync(0xffffffffu, pi[i], m);
            pf[i] += __shfl_xor_sync(0xffffffffu, pf[i], m);
            po[i] += __shfl_xor_sync(0xffffffffu, po[i], m);
        }
    }
    if ((lane & 3) == 0){
        #pragma unroll
        for (int mt = 0; mt < 2; ++mt)
        #pragma unroll
        for (int hf = 0; hf < 2; ++hf){
            int rl = m0w + mt*16 + (lane >> 2) + hf*8;
            sPart[(wn*3 + 0)*64 + rl] = pi[mt*2+hf];
            sPart[(wn*3 + 1)*64 + rl] = pf[mt*2+hf];
            sPart[(wn*3 + 2)*64 + rl] = po[mt*2+hf];
        }
    }
    __syncthreads();
    if (tid < 64){
        int r = tid;
        float si = 0.f, sf = 0.f, so = 0.f;
        #pragma unroll
        for (int w = 0; w < 4; ++w){
            si += sPart[(w*3 + 0)*64 + r];
            sf += sPart[(w*3 + 1)*64 + r];
            so += sPart[(w*3 + 2)*64 + r];
        }
        const float* srow = &sx[r*132];
        #pragma unroll 8
        for (int c = 0; c < 128; ++c){
            float xv = srow[c];
            si = fmaf(xv, sw[384 + c], si);
            sf = fmaf(xv, sw[512 + c], sf);
            so = fmaf(xv, sw[640 + c], so);
        }
        sGate[r]        = fast_sigmoid(si);
        sGate[64 + r]   = fast_sigmoid(sf);
        sGate[128 + r]  = fast_sigmoid(so);
    }
    __syncthreads();

    float* outb = out + ((size_t)b*N_ + pt*128 + mh*64)*D_;
    #pragma unroll
    for (int mt = 0; mt < 2; ++mt){
        #pragma unroll
        for (int nt = 0; nt < 4; ++nt){
            int c0 = n0 + nt*8 + ((lane & 3) << 1);
            const float* d = acc[mt][nt];
            #pragma unroll
            for (int hf = 0; hf < 2; ++hf){
                int rl = m0w + mt*16 + (lane >> 2) + hf*8;
                float ic = sGate[rl], fc = sGate[64 + rl], oc = sGate[128 + rl];
                float x0 = sx[rl*132 + c0], x1 = sx[rl*132 + c0 + 1];
                float h0 = fmaxf(d[hf*2], 0.f), h1 = fmaxf(d[hf*2+1], 0.f);
                float2 o;
                o.x = oc * fast_tanh(fmaf(ic, h0, fc*x0));
                o.y = oc * fast_tanh(fmaf(ic, h1, fc*x1));
                *(float2*)&outb[(size_t)rl*D_ + c0] = o;
            }
        }
    }
}

// ---------------------------------------------------------------------------
extern "C" void kernel_launch(void* const* d_in, const int* in_sizes, int n_in,
                              void* d_out, int out_size){
    const float* x   = (const float*)d_in[0];
    const float* adj = (const float*)d_in[1];
    const float* Ww  = (const float*)d_in[2];
    const float* Wb  = (const float*)d_in[3];
    const float* A   = (const float*)d_in[4];
    const float* wiu = (const float*)d_in[5];
    const float* wix = (const float*)d_in[6];
    const float* wfu = (const float*)d_in[7];
    const float* wfx = (const float*)d_in[8];
    const float* wou = (const float*)d_in[9];
    const float* wox = (const float*)d_in[10];
    float* out = (float*)d_out;

    cudaFuncSetAttribute(kB, cudaFuncAttributeMaxDynamicSharedMemorySize, SMEM_BYTES);
    cudaFuncSetAttribute(kC, cudaFuncAttributeMaxDynamicSharedMemorySize, SMEM_BYTES);
    cudaFuncSetAttribute(k_hg_mma, cudaFuncAttributeMaxDynamicSharedMemorySize, HG_SMEM);
    cudaFuncSetAttribute(k_hsT, cudaFuncAttributeMaxDynamicSharedMemorySize, 128*129*4);

    k_prep<<<64, 256>>>(Ww, A);
    k_prep2<<<65, 256>>>(Ww, Wb);
    k_wsplit<<<16, 256>>>();
    k_xsplit<<<1024, 256>>>(x);
    k_hg_mma<<<256, 256, HG_SMEM>>>();
    kB<<<dim3(8, 16, B_), 256, SMEM_BYTES>>>(adj);
    k_hsT<<<dim3(8, B_), 256, 128*129*4>>>();
    kC<<<dim3(8, 2, B_), 256, SMEM_BYTES>>>(x, wiu, wix, wfu, wfx, wou, wox, out);
}

// round 11
// speedup vs baseline: 1.2868x; 1.1021x over previous
#include <cuda_runtime.h>
#include <cuda_bf16.h>
#include <cstdint>

#define B_ 16
#define N_ 1024
#define D_ 128

// ---------------------------------------------------------------------------
// Scratch (device globals — no allocation allowed)
// Tile images: per 128x128 bf16 tile, 2 K-halves x 16KB, 128B swizzled rows.
// ---------------------------------------------------------------------------
__device__ float d_As[D_*D_];
__device__ float d_Wcat[D_*256];      // [WwT | W2] row k -> 256 cols
__device__ float d_bcat[256];         // [Wb | Wb@As]
__device__ float d_csum[B_*N_];
__device__ __nv_bfloat16 d_xH [B_*8*16384];
__device__ __nv_bfloat16 d_xL [B_*8*16384];
__device__ __nv_bfloat16 d_WcH[2*16384];
__device__ __nv_bfloat16 d_WcL[2*16384];
__device__ __nv_bfloat16 d_gsH[B_*8*16384];
__device__ __nv_bfloat16 d_gsL[B_*8*16384];
__device__ __nv_bfloat16 d_hH [B_*8*16384];
__device__ __nv_bfloat16 d_hL [B_*8*16384];
__device__ __nv_bfloat16 d_numH[(size_t)B_*N_*N_];   // 32 MB (hi only now)
__device__ __nv_bfloat16 d_hsTH[B_*8*16384];
__device__ __nv_bfloat16 d_hsTL[B_*8*16384];

// ---------------------------------------------------------------------------
// helpers (sm_80-era PTX only)
// ---------------------------------------------------------------------------
__device__ __forceinline__ uint32_t smem_to_u32(const void* p){
    uint32_t a;
    asm("{ .reg .u64 t; cvta.to.shared.u64 t, %1; cvt.u32.u64 %0, t; }" : "=r"(a) : "l"(p));
    return a;
}
__device__ __forceinline__ uint32_t hswz(int row, int kb){
    return (uint32_t)(row*128) + (uint32_t)(((((kb >> 4) ^ (row & 7)) & 7) << 4) | (kb & 15));
}
__device__ __forceinline__ void ldm4a(uint32_t addr, uint32_t r[4]){
    asm volatile("ldmatrix.sync.aligned.m8n8.x4.shared.b16 {%0,%1,%2,%3}, [%4];"
        : "=r"(r[0]), "=r"(r[1]), "=r"(r[2]), "=r"(r[3]) : "r"(addr));
}
__device__ __forceinline__ void mma16816(float* d, const uint32_t* a, uint32_t b0, uint32_t b1){
    asm volatile("mma.sync.aligned.m16n8k16.row.col.f32.bf16.bf16.f32 "
        "{%0,%1,%2,%3}, {%4,%5,%6,%7}, {%8,%9}, {%0,%1,%2,%3};"
        : "+f"(d[0]), "+f"(d[1]), "+f"(d[2]), "+f"(d[3])
        : "r"(a[0]), "r"(a[1]), "r"(a[2]), "r"(a[3]), "r"(b0), "r"(b1));
}
__device__ __forceinline__ void cpy(uint32_t sdst, const char* g, int tid, int n16){
    for (int i = tid; i < n16; i += 256){
        asm volatile("cp.async.cg.shared.global [%0], [%1], 16;"
            :: "r"(sdst + (uint32_t)i*16), "l"(g + (size_t)i*16));
    }
}
#define CP_COMMIT() asm volatile("cp.async.commit_group;" ::: "memory")
#define CP_WAIT(n)  asm volatile("cp.async.wait_group %0;" :: "n"(n) : "memory")

__device__ __forceinline__ void pack2(float a, float b, uint32_t& ph, uint32_t& pl){
    __nv_bfloat16 ah = __float2bfloat16(a), bh = __float2bfloat16(b);
    __nv_bfloat16 al = __float2bfloat16(a - __bfloat162float(ah));
    __nv_bfloat16 bl = __float2bfloat16(b - __bfloat162float(bh));
    ph = (uint32_t)__bfloat16_as_ushort(ah) | ((uint32_t)__bfloat16_as_ushort(bh) << 16);
    pl = (uint32_t)__bfloat16_as_ushort(al) | ((uint32_t)__bfloat16_as_ushort(bl) << 16);
}
__device__ __forceinline__ uint32_t packh(float a, float b){
    __nv_bfloat16 ah = __float2bfloat16(a), bh = __float2bfloat16(b);
    return (uint32_t)__bfloat16_as_ushort(ah) | ((uint32_t)__bfloat16_as_ushort(bh) << 16);
}
__device__ __forceinline__ float fast_sigmoid(float z){
    return __fdividef(1.f, 1.f + __expf(-z));
}
__device__ __forceinline__ float fast_tanh(float z){
    float t = __expf(2.f*z);
    return 1.f - __fdividef(2.f, t + 1.f);
}

// ---------------------------------------------------------------------------
// prep
// ---------------------------------------------------------------------------
__global__ void k_prep(const float* __restrict__ Ww, const float* __restrict__ A){
    int idx = blockIdx.x*256 + threadIdx.x;
    int r = idx >> 7, c = idx & 127;
    d_As[r*D_ + c]      = A[r*D_ + c] + A[c*D_ + r];
    d_Wcat[c*256 + r]   = Ww[r*D_ + c];
    d_csum[idx] = 0.f;
}
__global__ void k_prep2(const float* __restrict__ Ww, const float* __restrict__ Wb){
    if (blockIdx.x == 64){
        int c = threadIdx.x;
        if (c < 128){
            float s = 0.f;
            for (int d = 0; d < 128; ++d) s = fmaf(Wb[d], d_As[d*D_ + c], s);
            d_bcat[c] = Wb[c];
            d_bcat[128 + c] = s;
        }
        return;
    }
    int idx = blockIdx.x*256 + threadIdx.x;
    int k = idx >> 7, c = idx & 127;
    float s = 0.f;
    for (int j = 0; j < 128; ++j) s = fmaf(Ww[j*D_ + k], d_As[j*D_ + c], s);
    d_Wcat[k*256 + 128 + c] = s;
}
__global__ void k_wsplit(){
    int g = blockIdx.x*256 + threadIdx.x;
    int bt = g >> 11, rem = g & 2047;
    int n = rem >> 4, k8 = (rem & 15) << 3;
    float v[8];
    #pragma unroll
    for (int i = 0; i < 8; ++i) v[i] = d_Wcat[(size_t)(k8 + i)*256 + bt*128 + n];
    uint32_t h[4], l[4];
    #pragma unroll
    for (int i = 0; i < 4; ++i) pack2(v[2*i], v[2*i+1], h[i], l[i]);
    int kb = k8*2, half = kb >> 7;
    size_t base = (size_t)bt*32768 + (size_t)half*16384 + hswz(n, kb & 127);
    *(uint4*)((char*)d_WcH + base) = make_uint4(h[0],h[1],h[2],h[3]);
    *(uint4*)((char*)d_WcL + base) = make_uint4(l[0],l[1],l[2],l[3]);
}
__global__ void k_xsplit(const float* __restrict__ x){
    int g = blockIdx.x*256 + threadIdx.x;
    int tile = g >> 11, rem = g & 2047;
    int row = rem >> 4, c8 = (rem & 15) << 3;
    const float* sp = &x[((size_t)tile*128 + row)*D_ + c8];
    float v[8];
    *(float4*)v = *(const float4*)sp; *(float4*)(v+4) = *(const float4*)(sp+4);
    uint32_t h[4], l[4];
    #pragma unroll
    for (int i = 0; i < 4; ++i) pack2(v[2*i], v[2*i+1], h[i], l[i]);
    int kb = c8*2, half = kb >> 7;
    size_t base = (size_t)tile*32768 + (size_t)half*16384 + hswz(row, kb & 127);
    *(uint4*)((char*)d_xH + base) = make_uint4(h[0],h[1],h[2],h[3]);
    *(uint4*)((char*)d_xL + base) = make_uint4(l[0],l[1],l[2],l[3]);
}

// ---------------------------------------------------------------------------
// 3-term split MMA over one K-half; A image (aH@aB, aL@aB+8K, 64 rows),
// B image (bH@bB, bL@bB+16K, 128 rows). warp grid 2m x 4n, acc[2][4][4].
// ---------------------------------------------------------------------------
__device__ __forceinline__ void mma_half2(uint32_t aB, uint32_t bB,
                                          int m0w, int n0, float acc[2][4][4]){
    int lane = threadIdx.x & 31;
    int lrow = lane & 15;
    uint32_t lk = (uint32_t)((lane >> 4) << 4);
    uint32_t aHa[2], aLa[2], bHa[2], bLa[2];
    #pragma unroll
    for (int mt = 0; mt < 2; ++mt){
        uint32_t o = hswz(m0w + mt*16 + lrow, lk);
        aHa[mt] = aB + o; aLa[mt] = aB + 8192 + o;
    }
    #pragma unroll
    for (int np = 0; np < 2; ++np){
        uint32_t o = hswz(n0 + np*16 + lrow, lk);
        bHa[np] = bB + o; bLa[np] = bB + 16384 + o;
    }
    #pragma unroll
    for (int k4 = 0; k4 < 4; ++k4){
        uint32_t xo = (uint32_t)(k4 << 5);
        uint32_t aH[2][4], aL[2][4], bH[2][4], bL[2][4];
        #pragma unroll
        for (int mt = 0; mt < 2; ++mt){ ldm4a(aHa[mt]^xo, aH[mt]); ldm4a(aLa[mt]^xo, aL[mt]); }
        #pragma unroll
        for (int np = 0; np < 2; ++np){ ldm4a(bHa[np]^xo, bH[np]); ldm4a(bLa[np]^xo, bL[np]); }
        #pragma unroll
        for (int mt = 0; mt < 2; ++mt)
        #pragma unroll
        for (int np = 0; np < 2; ++np)
        #pragma unroll
        for (int hf = 0; hf < 2; ++hf){
            float* d = acc[mt][np*2 + hf];
            mma16816(d, aH[mt], bH[np][hf], bH[np][2 + hf]);
            mma16816(d, aH[mt], bL[np][hf], bL[np][2 + hf]);
            mma16816(d, aL[mt], bH[np][hf], bH[np][2 + hf]);
        }
    }
}
// 2-term variant: A hi-only (aH@aB, 64 rows); terms AH*BH + AH*BL
__device__ __forceinline__ void mma_half2t(uint32_t aB, uint32_t bB,
                                           int m0w, int n0, float acc[2][4][4]){
    int lane = threadIdx.x & 31;
    int lrow = lane & 15;
    uint32_t lk = (uint32_t)((lane >> 4) << 4);
    uint32_t aHa[2], bHa[2], bLa[2];
    #pragma unroll
    for (int mt = 0; mt < 2; ++mt)
        aHa[mt] = aB + hswz(m0w + mt*16 + lrow, lk);
    #pragma unroll
    for (int np = 0; np < 2; ++np){
        uint32_t o = hswz(n0 + np*16 + lrow, lk);
        bHa[np] = bB + o; bLa[np] = bB + 16384 + o;
    }
    #pragma unroll
    for (int k4 = 0; k4 < 4; ++k4){
        uint32_t xo = (uint32_t)(k4 << 5);
        uint32_t aH[2][4], bH[2][4], bL[2][4];
        #pragma unroll
        for (int mt = 0; mt < 2; ++mt) ldm4a(aHa[mt]^xo, aH[mt]);
        #pragma unroll
        for (int np = 0; np < 2; ++np){ ldm4a(bHa[np]^xo, bH[np]); ldm4a(bLa[np]^xo, bL[np]); }
        #pragma unroll
        for (int mt = 0; mt < 2; ++mt)
        #pragma unroll
        for (int np = 0; np < 2; ++np)
        #pragma unroll
        for (int hf = 0; hf < 2; ++hf){
            float* d = acc[mt][np*2 + hf];
            mma16816(d, aH[mt], bH[np][hf], bH[np][2 + hf]);
            mma16816(d, aH[mt], bL[np][hf], bL[np][2 + hf]);
        }
    }
}

// ---------------------------------------------------------------------------
// k_hg_mma: [h | gs] = x @ [Ww^T | W2] + bcat via split HMMA.
// ---------------------------------------------------------------------------
#define HG_B 32768
#define HG_SMEM 65536

__global__ void __launch_bounds__(256, 2) k_hg_mma(){
    extern __shared__ char smem[];
    uint32_t sb = smem_to_u32(smem);
    int tid = threadIdx.x, lane = tid & 31, wid = tid >> 5;
    int tile = blockIdx.x >> 1, mrow = blockIdx.x & 1;
    int m0w = (wid >> 2)*32, n0 = (wid & 3)*32;

    size_t gax = (size_t)tile*32768 + (size_t)mrow*8192;
    cpy(sb,         (const char*)d_xH + gax,         tid, 512);
    cpy(sb + 8192,  (const char*)d_xL + gax,         tid, 512);
    cpy(sb + 16384, (const char*)d_xH + gax + 16384, tid, 512);
    cpy(sb + 24576, (const char*)d_xL + gax + 16384, tid, 512);
    CP_COMMIT();

    for (int bt = 0; bt < 2; ++bt){
        float acc[2][4][4] = {};
        for (int half = 0; half < 2; ++half){
            size_t gw = (size_t)bt*32768 + (size_t)half*16384;
            cpy(sb + HG_B,         (const char*)d_WcH + gw, tid, 1024);
            cpy(sb + HG_B + 16384, (const char*)d_WcL + gw, tid, 1024);
            CP_COMMIT();
            CP_WAIT(0);
            __syncthreads();
            mma_half2(sb + (uint32_t)half*16384, sb + HG_B, m0w, n0, acc);
            __syncthreads();
        }
        char* stH = smem + HG_B;
        char* stL = smem + HG_B + 16384;
        #pragma unroll
        for (int mt = 0; mt < 2; ++mt){
            int r1 = m0w + mt*16 + (lane >> 2);
            #pragma unroll
            for (int nt = 0; nt < 4; ++nt){
                int c0 = n0 + nt*8 + ((lane & 3) << 1);
                float b0 = d_bcat[bt*128 + c0], b1 = d_bcat[bt*128 + c0 + 1];
                const float* d = acc[mt][nt];
                #pragma unroll
                for (int hf = 0; hf < 2; ++hf){
                    int r = r1 + hf*8;
                    uint32_t ph, pl; pack2(d[hf*2] + b0, d[hf*2+1] + b1, ph, pl);
                    int kb = c0*2, half = kb >> 7;
                    uint32_t off = (uint32_t)half*8192 + hswz(r, kb & 127);
                    *(uint32_t*)(stH + off) = ph;
                    *(uint32_t*)(stL + off) = pl;
                }
            }
        }
        __syncthreads();
        char* gH = (char*)(bt ? d_gsH : d_hH);
        char* gL = (char*)(bt ? d_gsL : d_hL);
        #pragma unroll
        for (int half = 0; half < 2; ++half){
            size_t gb = (size_t)tile*32768 + (size_t)half*16384 + (size_t)mrow*8192;
            uint4* dH = (uint4*)(gH + gb); uint4* dL = (uint4*)(gL + gb);
            const uint4* sH = (const uint4*)(stH + half*8192);
            const uint4* sL = (const uint4*)(stL + half*8192);
            for (int i = tid; i < 512; i += 256){ dH[i] = sH[i]; dL[i] = sL[i]; }
        }
        __syncthreads();
    }
}

// ---------------------------------------------------------------------------
// k_hsT: hsT[d][q] = h[q][d]/csum[q]  (h from hi/lo images)
// ---------------------------------------------------------------------------
__global__ void k_hsT(){
    extern __shared__ float sT[];   // 128*129
    int qc = blockIdx.x, b = blockIdx.y, tid = threadIdx.x;
    size_t tileB = (size_t)(b*8 + qc)*32768;
    for (int g = tid; g < 2048; g += 256){
        int q = g >> 4, col8 = (g & 15) << 3;
        int kb = col8*2, half = kb >> 7, kb2 = kb & 127;
        size_t base = tileB + (size_t)half*16384 + hswz(q, kb2);
        uint4 uh = *(const uint4*)((const char*)d_hH + base);
        uint4 ul = *(const uint4*)((const char*)d_hL + base);
        float r = 1.0f / d_csum[b*N_ + qc*128 + q];
        const uint32_t wh[4] = {uh.x,uh.y,uh.z,uh.w};
        const uint32_t wl[4] = {ul.x,ul.y,ul.z,ul.w};
        #pragma unroll
        for (int t = 0; t < 4; ++t){
            float v0 = __bfloat162float(__ushort_as_bfloat16((unsigned short)(wh[t] & 0xffff)))
                     + __bfloat162float(__ushort_as_bfloat16((unsigned short)(wl[t] & 0xffff)));
            float v1 = __bfloat162float(__ushort_as_bfloat16((unsigned short)(wh[t] >> 16)))
                     + __bfloat162float(__ushort_as_bfloat16((unsigned short)(wl[t] >> 16)));
            sT[(col8 + 2*t)*129 + q]     = v0*r;
            sT[(col8 + 2*t + 1)*129 + q] = v1*r;
        }
    }
    __syncthreads();
    for (int g = tid; g < 2048; g += 256){
        int dd = g >> 4, q8 = (g & 15) << 3;
        int kb = q8*2, half = kb >> 7, kb2 = kb & 127;
        uint32_t h[4], l[4];
        #pragma unroll
        for (int i = 0; i < 4; ++i)
            pack2(sT[dd*129 + q8 + 2*i], sT[dd*129 + q8 + 2*i + 1], h[i], l[i]);
        size_t base = tileB + (size_t)half*16384 + hswz(dd, kb2);
        *(uint4*)((char*)d_hsTH + base) = make_uint4(h[0],h[1],h[2],h[3]);
        *(uint4*)((char*)d_hsTL + base) = make_uint4(l[0],l[1],l[2],l[3]);
    }
}

// ---------------------------------------------------------------------------
// kB stage layout: aH 0 | aL 8K | bH 16K | bL 32K (48KB); two stages = 96KB
// ---------------------------------------------------------------------------
#define ST_AL 8192
#define ST_BH 16384
#define ST_BL 32768
#define ST_SZ 49152
#define SMEM_BYTES (2*ST_SZ + 512)

// ---------------------------------------------------------------------------
// kB: e = gs @ h^T; fused mask/__expf/colsum epilogue; numer hi -> images.
// grid (8,16,16)
// ---------------------------------------------------------------------------
__global__ void __launch_bounds__(256, 2) kB(const float* __restrict__ adj){
    extern __shared__ char smem[];
    uint32_t sb = smem_to_u32(smem);
    int tid = threadIdx.x, lane = tid & 31, wid = tid >> 5;
    int qt = blockIdx.x, pth = blockIdx.y, b = blockIdx.z;
    int ptc = pth >> 1, mrow = pth & 1;
    int m0w = (wid >> 2)*32, n0 = (wid & 3)*32;

    size_t ga = (size_t)(b*8 + ptc)*32768 + (size_t)mrow*8192;
    size_t gb = (size_t)(b*8 + qt)*32768;

    cpy(sb,          (const char*)d_gsH + ga, tid, 512);
    cpy(sb + ST_AL,  (const char*)d_gsL + ga, tid, 512);
    cpy(sb + ST_BH,  (const char*)d_hH  + gb, tid, 1024);
    cpy(sb + ST_BL,  (const char*)d_hL  + gb, tid, 1024);
    CP_COMMIT();

    float acc[2][4][4] = {};
    {
        uint32_t s1 = sb + ST_SZ;
        cpy(s1,         (const char*)d_gsH + ga + 16384, tid, 512);
        cpy(s1 + ST_AL, (const char*)d_gsL + ga + 16384, tid, 512);
        cpy(s1 + ST_BH, (const char*)d_hH  + gb + 16384, tid, 1024);
        cpy(s1 + ST_BL, (const char*)d_hL  + gb + 16384, tid, 1024);
        CP_COMMIT();
        CP_WAIT(1);
        __syncthreads();
        mma_half2(sb, sb + ST_BH, m0w, n0, acc);
        CP_WAIT(0);
        __syncthreads();
        mma_half2(sb + ST_SZ, sb + ST_SZ + ST_BH, m0w, n0, acc);
        __syncthreads();
    }

    float* scol = (float*)(smem + 2*ST_SZ);
    if (tid < 128) scol[tid] = 0.f;
    __syncthreads();

    const float* adjb = adj + (size_t)b*N_*N_ + (size_t)(pth*64)*N_ + qt*128;
    char* stH = smem;
    float cs[8] = {};
    #pragma unroll
    for (int mt = 0; mt < 2; ++mt){
        int r1 = m0w + mt*16 + (lane >> 2);
        #pragma unroll
        for (int nt = 0; nt < 4; ++nt){
            int c0 = n0 + nt*8 + ((lane & 3) << 1);
            const float* d = acc[mt][nt];
            #pragma unroll
            for (int hf = 0; hf < 2; ++hf){
                int r = r1 + hf*8;
                float2 av = *(const float2*)&adjb[(size_t)r*N_ + c0];
                float e0 = d[hf*2 + 0], e1 = d[hf*2 + 1];
                float ev0 = (av.x > 0.f) ? __expf(e0) : 1.f;
                float ev1 = (av.y > 0.f) ? __expf(e1) : 1.f;
                float nv0 = (av.x > 0.f) ? ev0 : 0.f;
                float nv1 = (av.y > 0.f) ? ev1 : 0.f;
                cs[nt*2 + 0] += ev0; cs[nt*2 + 1] += ev1;
                int kb = c0*2, half = kb >> 7;
                uint32_t off = (uint32_t)half*8192 + hswz(r, kb & 127);
                *(uint32_t*)(stH + off) = packh(nv0, nv1);
            }
        }
    }
    #pragma unroll
    for (int m = 4; m < 32; m <<= 1){
        #pragma unroll
        for (int i = 0; i < 8; ++i) cs[i] += __shfl_xor_sync(0xffffffffu, cs[i], m);
    }
    if (lane < 4){
        #pragma unroll
        for (int nt = 0; nt < 4; ++nt){
            atomicAdd(&scol[n0 + nt*8 + 2*lane],     cs[nt*2]);
            atomicAdd(&scol[n0 + nt*8 + 2*lane + 1], cs[nt*2 + 1]);
        }
    }
    __syncthreads();
    if (tid < 128) atomicAdd(&d_csum[b*N_ + qt*128 + tid], scol[tid]);

    size_t tnum = (size_t)(b*64 + ptc*8 + qt)*32768 + (size_t)mrow*8192;
    #pragma unroll
    for (int half = 0; half < 2; ++half){
        uint4* gH = (uint4*)((char*)d_numH + tnum + (size_t)half*16384);
        const uint4* sH = (const uint4*)(stH + half*8192);
        for (int i = tid; i < 512; i += 256) gH[i] = sH[i];
    }
}

// ---------------------------------------------------------------------------
// kC stage layout: aH 0 | bH 8K | bL 24K (40KB); two stages = 80KB
// ---------------------------------------------------------------------------
#define C_BH 8192
#define C_BL 24576
#define C_SZ 40960
#define C_SMEM (2*C_SZ)

// ---------------------------------------------------------------------------
// kC: h' = numer(hi) @ hsT^T (2-term), 16 pipelined K-half steps,
// fused gates epilogue. grid (8, 2, 16)
// ---------------------------------------------------------------------------
__global__ void __launch_bounds__(256, 2) kC(const float* __restrict__ x,
        const float* __restrict__ wiu, const float* __restrict__ wix,
        const float* __restrict__ wfu, const float* __restrict__ wfx,
        const float* __restrict__ wou, const float* __restrict__ wox,
        float* __restrict__ out){
    extern __shared__ char smem[];
    uint32_t sb = smem_to_u32(smem);
    int tid = threadIdx.x, lane = tid & 31, wid = tid >> 5;
    int pt = blockIdx.x, mh = blockIdx.y, b = blockIdx.z;
    int m0w = (wid >> 2)*32, n0 = (wid & 3)*32, wn = wid & 3;

    {
        size_t ta = (size_t)(b*64 + pt*8)*32768 + (size_t)mh*8192;
        size_t tb = (size_t)(b*8)*32768;
        cpy(sb,        (const char*)d_numH + ta, tid, 512);
        cpy(sb + C_BH, (const char*)d_hsTH + tb, tid, 1024);
        cpy(sb + C_BL, (const char*)d_hsTL + tb, tid, 1024);
        CP_COMMIT();
    }

    float acc[2][4][4] = {};
    for (int t = 0; t < 16; ++t){
        if (t < 15){
            int tn = t + 1, qc = tn >> 1, kh = tn & 1;
            uint32_t s = sb + (uint32_t)((tn & 1) ? C_SZ : 0);
            size_t ta = (size_t)(b*64 + pt*8 + qc)*32768 + (size_t)kh*16384 + (size_t)mh*8192;
            size_t tb = (size_t)(b*8 + qc)*32768 + (size_t)kh*16384;
            cpy(s,        (const char*)d_numH + ta, tid, 512);
            cpy(s + C_BH, (const char*)d_hsTH + tb, tid, 1024);
            cpy(s + C_BL, (const char*)d_hsTL + tb, tid, 1024);
            CP_COMMIT();
            CP_WAIT(1);
        } else {
            CP_WAIT(0);
        }
        __syncthreads();
        uint32_t st = sb + (uint32_t)((t & 1) ? C_SZ : 0);
        mma_half2t(st, st + C_BH, m0w, n0, acc);
        __syncthreads();
    }

    float* sx    = (float*)smem;                 // [64][132]
    float* sw    = (float*)(smem + 33792);       // [6][128]
    float* sPart = (float*)(smem + 36864);       // [4 wn][3][64]
    float* sGate = (float*)(smem + 39936);       // [3][64]
    const float* xb = x + ((size_t)b*N_ + pt*128 + mh*64)*D_;
    for (int g = tid; g < 2048; g += 256){
        int row = g >> 5, c4 = (g & 31) << 2;
        float4 v = *(const float4*)&xb[(size_t)row*D_ + c4];
        float* p = &sx[row*132 + c4];
        p[0]=v.x; p[1]=v.y; p[2]=v.z; p[3]=v.w;
    }
    if (tid < 128){
        sw[tid]       = wiu[tid]; sw[128 + tid] = wfu[tid]; sw[256 + tid] = wou[tid];
        sw[384 + tid] = wix[tid]; sw[512 + tid] = wfx[tid]; sw[640 + tid] = wox[tid];
    }
    __syncthreads();

    float pi[4] = {}, pf[4] = {}, po[4] = {};
    #pragma unroll
    for (int mt = 0; mt < 2; ++mt){
        #pragma unroll
        for (int nt = 0; nt < 4; ++nt){
            int c0 = n0 + nt*8 + ((lane & 3) << 1);
            float wi0 = sw[c0], wi1 = sw[c0+1];
            float wf0 = sw[128+c0], wf1 = sw[129+c0];
            float wo0 = sw[256+c0], wo1 = sw[257+c0];
            const float* d = acc[mt][nt];
            #pragma unroll
            for (int hf = 0; hf < 2; ++hf){
                float h0 = fmaxf(d[hf*2], 0.f), h1 = fmaxf(d[hf*2+1], 0.f);
                pi[mt*2+hf] += h0*wi0 + h1*wi1;
                pf[mt*2+hf] += h0*wf0 + h1*wf1;
                po[mt*2+hf] += h0*wo0 + h1*wo1;
            }
        }
    }
    #pragma unroll
    for (int m = 1; m < 4; m <<= 1){
        #pragma unroll
        for (int i = 0; i < 4; ++i){
            pi[i] += __shfl_xor_sync(0xffffffffu, pi[i], m);
            pf[i] += __shfl_xor_sync(0xffffffffu, pf[i], m);
            po[i] += __shfl_xor_sync(0xffffffffu, po[i], m);
        }
    }
    if ((lane & 3) == 0){
        #pragma unroll
        for (int mt = 0; mt < 2; ++mt)
        #pragma unroll
        for (int hf = 0; hf < 2; ++hf){
            int rl = m0w + mt*16 + (lane >> 2) + hf*8;
            sPart[(wn*3 + 0)*64 + rl] = pi[mt*2+hf];
            sPart[(wn*3 + 1)*64 + rl] = pf[mt*2+hf];
            sPart[(wn*3 + 2)*64 + rl] = po[mt*2+hf];
        }
    }
    __syncthreads();
    if (tid < 64){
        int r = tid;
        float si = 0.f, sf = 0.f, so = 0.f;
        #pragma unroll
        for (int w = 0; w < 4; ++w){
            si += sPart[(w*3 + 0)*64 + r];
            sf += sPart[(w*3 + 1)*64 + r];
            so += sPart[(w*3 + 2)*64 + r];
        }
        const float* srow = &sx[r*132];
        #pragma unroll 8
        for (int c = 0; c < 128; ++c){
            float xv = srow[c];
            si = fmaf(xv, sw[384 + c], si);
            sf = fmaf(xv, sw[512 + c], sf);
            so = fmaf(xv, sw[640 + c], so);
        }
        sGate[r]        = fast_sigmoid(si);
        sGate[64 + r]   = fast_sigmoid(sf);
        sGate[128 + r]  = fast_sigmoid(so);
    }
    __syncthreads();

    float* outb = out + ((size_t)b*N_ + pt*128 + mh*64)*D_;
    #pragma unroll
    for (int mt = 0; mt < 2; ++mt){
        #pragma unroll
        for (int nt = 0; nt < 4; ++nt){
            int c0 = n0 + nt*8 + ((lane & 3) << 1);
            const float* d = acc[mt][nt];
            #pragma unroll
            for (int hf = 0; hf < 2; ++hf){
                int rl = m0w + mt*16 + (lane >> 2) + hf*8;
                float ic = sGate[rl], fc = sGate[64 + rl], oc = sGate[128 + rl];
                float x0 = sx[rl*132 + c0], x1 = sx[rl*132 + c0 + 1];
                float h0 = fmaxf(d[hf*2], 0.f), h1 = fmaxf(d[hf*2+1], 0.f);
                float2 o;
                o.x = oc * fast_tanh(fmaf(ic, h0, fc*x0));
                o.y = oc * fast_tanh(fmaf(ic, h1, fc*x1));
                *(float2*)&outb[(size_t)rl*D_ + c0] = o;
            }
        }
    }
}

// ---------------------------------------------------------------------------
extern "C" void kernel_launch(void* const* d_in, const int* in_sizes, int n_in,
                              void* d_out, int out_size){
    const float* x   = (const float*)d_in[0];
    const float* adj = (const float*)d_in[1];
    const float* Ww  = (const float*)d_in[2];
    const float* Wb  = (const float*)d_in[3];
    const float* A   = (const float*)d_in[4];
    const float* wiu = (const float*)d_in[5];
    const float* wix = (const float*)d_in[6];
    const float* wfu = (const float*)d_in[7];
    const float* wfx = (const float*)d_in[8];
    const float* wou = (const float*)d_in[9];
    const float* wox = (const float*)d_in[10];
    float* out = (float*)d_out;

    cudaFuncSetAttribute(kB, cudaFuncAttributeMaxDynamicSharedMemorySize, SMEM_BYTES);
    cudaFuncSetAttribute(kC, cudaFuncAttributeMaxDynamicSharedMemorySize, C_SMEM);
    cudaFuncSetAttribute(k_hg_mma, cudaFuncAttributeMaxDynamicSharedMemorySize, HG_SMEM);
    cudaFuncSetAttribute(k_hsT, cudaFuncAttributeMaxDynamicSharedMemorySize, 128*129*4);

    k_prep<<<64, 256>>>(Ww, A);
    k_prep2<<<65, 256>>>(Ww, Wb);
    k_wsplit<<<16, 256>>>();
    k_xsplit<<<1024, 256>>>(x);
    k_hg_mma<<<256, 256, HG_SMEM>>>();
    kB<<<dim3(8, 16, B_), 256, SMEM_BYTES>>>(adj);
    k_hsT<<<dim3(8, B_), 256, 128*129*4>>>();
    kC<<<dim3(8, 2, B_), 256, C_SMEM>>>(x, wiu, wix, wfu, wfx, wou, wox, out);
}

// round 12
// speedup vs baseline: 1.3642x; 1.0602x over previous
#include <cuda_runtime.h>
#include <cuda_bf16.h>
#include <cstdint>

#define B_ 16
#define N_ 1024
#define D_ 128

// ---------------------------------------------------------------------------
// Scratch (device globals — no allocation allowed)
// Tile images: per 128x128 bf16 tile, 2 K-halves x 16KB, 128B swizzled rows.
// ---------------------------------------------------------------------------
__device__ float d_As[D_*D_];
__device__ float d_Wcat[D_*256];      // [WwT | W2] row k -> 256 cols
__device__ float d_bcat[256];         // [Wb | Wb@As]
__device__ float d_csum[B_*N_];
__device__ __nv_bfloat16 d_WcH[2*16384];
__device__ __nv_bfloat16 d_WcL[2*16384];
__device__ __nv_bfloat16 d_gsH[B_*8*16384];
__device__ __nv_bfloat16 d_gsL[B_*8*16384];
__device__ __nv_bfloat16 d_hH [B_*8*16384];
__device__ __nv_bfloat16 d_hL [B_*8*16384];
__device__ __nv_bfloat16 d_numH[(size_t)B_*N_*N_];   // 32 MB (hi only)
__device__ __nv_bfloat16 d_hsTH[B_*8*16384];
__device__ __nv_bfloat16 d_hsTL[B_*8*16384];

// ---------------------------------------------------------------------------
// helpers (sm_80-era PTX only)
// ---------------------------------------------------------------------------
__device__ __forceinline__ uint32_t smem_to_u32(const void* p){
    uint32_t a;
    asm("{ .reg .u64 t; cvta.to.shared.u64 t, %1; cvt.u32.u64 %0, t; }" : "=r"(a) : "l"(p));
    return a;
}
__device__ __forceinline__ uint32_t hswz(int row, int kb){
    return (uint32_t)(row*128) + (uint32_t)(((((kb >> 4) ^ (row & 7)) & 7) << 4) | (kb & 15));
}
__device__ __forceinline__ void ldm4a(uint32_t addr, uint32_t r[4]){
    asm volatile("ldmatrix.sync.aligned.m8n8.x4.shared.b16 {%0,%1,%2,%3}, [%4];"
        : "=r"(r[0]), "=r"(r[1]), "=r"(r[2]), "=r"(r[3]) : "r"(addr));
}
__device__ __forceinline__ void mma16816(float* d, const uint32_t* a, uint32_t b0, uint32_t b1){
    asm volatile("mma.sync.aligned.m16n8k16.row.col.f32.bf16.bf16.f32 "
        "{%0,%1,%2,%3}, {%4,%5,%6,%7}, {%8,%9}, {%0,%1,%2,%3};"
        : "+f"(d[0]), "+f"(d[1]), "+f"(d[2]), "+f"(d[3])
        : "r"(a[0]), "r"(a[1]), "r"(a[2]), "r"(a[3]), "r"(b0), "r"(b1));
}
__device__ __forceinline__ void cpy(uint32_t sdst, const char* g, int tid, int n16){
    for (int i = tid; i < n16; i += 256){
        asm volatile("cp.async.cg.shared.global [%0], [%1], 16;"
            :: "r"(sdst + (uint32_t)i*16), "l"(g + (size_t)i*16));
    }
}
#define CP_COMMIT() asm volatile("cp.async.commit_group;" ::: "memory")
#define CP_WAIT(n)  asm volatile("cp.async.wait_group %0;" :: "n"(n) : "memory")

__device__ __forceinline__ void pack2(float a, float b, uint32_t& ph, uint32_t& pl){
    __nv_bfloat16 ah = __float2bfloat16(a), bh = __float2bfloat16(b);
    __nv_bfloat16 al = __float2bfloat16(a - __bfloat162float(ah));
    __nv_bfloat16 bl = __float2bfloat16(b - __bfloat162float(bh));
    ph = (uint32_t)__bfloat16_as_ushort(ah) | ((uint32_t)__bfloat16_as_ushort(bh) << 16);
    pl = (uint32_t)__bfloat16_as_ushort(al) | ((uint32_t)__bfloat16_as_ushort(bl) << 16);
}
__device__ __forceinline__ uint32_t packh(float a, float b){
    __nv_bfloat16 ah = __float2bfloat16(a), bh = __float2bfloat16(b);
    return (uint32_t)__bfloat16_as_ushort(ah) | ((uint32_t)__bfloat16_as_ushort(bh) << 16);
}
__device__ __forceinline__ float fast_sigmoid(float z){
    return __fdividef(1.f, 1.f + __expf(-z));
}
__device__ __forceinline__ float fast_tanh(float z){
    float t = __expf(2.f*z);
    return 1.f - __fdividef(2.f, t + 1.f);
}

// ---------------------------------------------------------------------------
// prep
// ---------------------------------------------------------------------------
__global__ void k_prep(const float* __restrict__ Ww, const float* __restrict__ A){
    int idx = blockIdx.x*256 + threadIdx.x;
    int r = idx >> 7, c = idx & 127;
    d_As[r*D_ + c]      = A[r*D_ + c] + A[c*D_ + r];
    d_Wcat[c*256 + r]   = Ww[r*D_ + c];
    d_csum[idx] = 0.f;
}
__global__ void k_prep2(const float* __restrict__ Ww, const float* __restrict__ Wb){
    if (blockIdx.x == 64){
        int c = threadIdx.x;
        if (c < 128){
            float s = 0.f;
            for (int d = 0; d < 128; ++d) s = fmaf(Wb[d], d_As[d*D_ + c], s);
            d_bcat[c] = Wb[c];
            d_bcat[128 + c] = s;
        }
        return;
    }
    int idx = blockIdx.x*256 + threadIdx.x;
    int k = idx >> 7, c = idx & 127;
    float s = 0.f;
    for (int j = 0; j < 128; ++j) s = fmaf(Ww[j*D_ + k], d_As[j*D_ + c], s);
    d_Wcat[k*256 + 128 + c] = s;
}
__global__ void k_wsplit(){
    int g = blockIdx.x*256 + threadIdx.x;
    int bt = g >> 11, rem = g & 2047;
    int n = rem >> 4, k8 = (rem & 15) << 3;
    float v[8];
    #pragma unroll
    for (int i = 0; i < 8; ++i) v[i] = d_Wcat[(size_t)(k8 + i)*256 + bt*128 + n];
    uint32_t h[4], l[4];
    #pragma unroll
    for (int i = 0; i < 4; ++i) pack2(v[2*i], v[2*i+1], h[i], l[i]);
    int kb = k8*2, half = kb >> 7;
    size_t base = (size_t)bt*32768 + (size_t)half*16384 + hswz(n, kb & 127);
    *(uint4*)((char*)d_WcH + base) = make_uint4(h[0],h[1],h[2],h[3]);
    *(uint4*)((char*)d_WcL + base) = make_uint4(l[0],l[1],l[2],l[3]);
}

// ---------------------------------------------------------------------------
// 3-term split MMA over one K-half; A image (aH@aB, aL@aB+8K, 64 rows),
// B image (bH@bB, bL@bB+16K, 128 rows). warp grid 2m x 4n, acc[2][4][4].
// ---------------------------------------------------------------------------
__device__ __forceinline__ void mma_half2(uint32_t aB, uint32_t bB,
                                          int m0w, int n0, float acc[2][4][4]){
    int lane = threadIdx.x & 31;
    int lrow = lane & 15;
    uint32_t lk = (uint32_t)((lane >> 4) << 4);
    uint32_t aHa[2], aLa[2], bHa[2], bLa[2];
    #pragma unroll
    for (int mt = 0; mt < 2; ++mt){
        uint32_t o = hswz(m0w + mt*16 + lrow, lk);
        aHa[mt] = aB + o; aLa[mt] = aB + 8192 + o;
    }
    #pragma unroll
    for (int np = 0; np < 2; ++np){
        uint32_t o = hswz(n0 + np*16 + lrow, lk);
        bHa[np] = bB + o; bLa[np] = bB + 16384 + o;
    }
    #pragma unroll
    for (int k4 = 0; k4 < 4; ++k4){
        uint32_t xo = (uint32_t)(k4 << 5);
        uint32_t aH[2][4], aL[2][4], bH[2][4], bL[2][4];
        #pragma unroll
        for (int mt = 0; mt < 2; ++mt){ ldm4a(aHa[mt]^xo, aH[mt]); ldm4a(aLa[mt]^xo, aL[mt]); }
        #pragma unroll
        for (int np = 0; np < 2; ++np){ ldm4a(bHa[np]^xo, bH[np]); ldm4a(bLa[np]^xo, bL[np]); }
        #pragma unroll
        for (int mt = 0; mt < 2; ++mt)
        #pragma unroll
        for (int np = 0; np < 2; ++np)
        #pragma unroll
        for (int hf = 0; hf < 2; ++hf){
            float* d = acc[mt][np*2 + hf];
            mma16816(d, aH[mt], bH[np][hf], bH[np][2 + hf]);
            mma16816(d, aH[mt], bL[np][hf], bL[np][2 + hf]);
            mma16816(d, aL[mt], bH[np][hf], bH[np][2 + hf]);
        }
    }
}
// 2-term variant: A hi-only
__device__ __forceinline__ void mma_half2t(uint32_t aB, uint32_t bB,
                                           int m0w, int n0, float acc[2][4][4]){
    int lane = threadIdx.x & 31;
    int lrow = lane & 15;
    uint32_t lk = (uint32_t)((lane >> 4) << 4);
    uint32_t aHa[2], bHa[2], bLa[2];
    #pragma unroll
    for (int mt = 0; mt < 2; ++mt)
        aHa[mt] = aB + hswz(m0w + mt*16 + lrow, lk);
    #pragma unroll
    for (int np = 0; np < 2; ++np){
        uint32_t o = hswz(n0 + np*16 + lrow, lk);
        bHa[np] = bB + o; bLa[np] = bB + 16384 + o;
    }
    #pragma unroll
    for (int k4 = 0; k4 < 4; ++k4){
        uint32_t xo = (uint32_t)(k4 << 5);
        uint32_t aH[2][4], bH[2][4], bL[2][4];
        #pragma unroll
        for (int mt = 0; mt < 2; ++mt) ldm4a(aHa[mt]^xo, aH[mt]);
        #pragma unroll
        for (int np = 0; np < 2; ++np){ ldm4a(bHa[np]^xo, bH[np]); ldm4a(bLa[np]^xo, bL[np]); }
        #pragma unroll
        for (int mt = 0; mt < 2; ++mt)
        #pragma unroll
        for (int np = 0; np < 2; ++np)
        #pragma unroll
        for (int hf = 0; hf < 2; ++hf){
            float* d = acc[mt][np*2 + hf];
            mma16816(d, aH[mt], bH[np][hf], bH[np][2 + hf]);
            mma16816(d, aH[mt], bL[np][hf], bL[np][2 + hf]);
        }
    }
}

// ---------------------------------------------------------------------------
// k_hg_mma: [h | gs] = x @ [Ww^T | W2] + bcat via split HMMA.
// x loaded fp32 and split in-kernel to smem images (no global image round trip).
// ---------------------------------------------------------------------------
#define HG_B 32768
#define HG_SMEM 65536

__global__ void __launch_bounds__(256, 2) k_hg_mma(const float* __restrict__ x){
    extern __shared__ char smem[];
    uint32_t sb = smem_to_u32(smem);
    int tid = threadIdx.x, lane = tid & 31, wid = tid >> 5;
    int tile = blockIdx.x >> 1, mrow = blockIdx.x & 1;
    int m0w = (wid >> 2)*32, n0 = (wid & 3)*32;

    // issue first weight group early
    cpy(sb + HG_B,         (const char*)d_WcH, tid, 1024);
    cpy(sb + HG_B + 16384, (const char*)d_WcL, tid, 1024);
    CP_COMMIT();

    // load x fp32 (coalesced) and split to smem images: half*16384 + {hi, +8192 lo}
    int rbase = tile*128 + mrow*64;
    for (int g = tid; g < 1024; g += 256){
        int row = g >> 4, c8 = (g & 15) << 3;
        const float* sp = &x[((size_t)(rbase + row))*D_ + c8];
        float v[8];
        *(float4*)v = *(const float4*)sp; *(float4*)(v+4) = *(const float4*)(sp+4);
        uint32_t h[4], l[4];
        #pragma unroll
        for (int i = 0; i < 4; ++i) pack2(v[2*i], v[2*i+1], h[i], l[i]);
        int kb = c8*2, half = kb >> 7;
        uint32_t off = (uint32_t)(half*16384) + hswz(row, kb & 127);
        *(uint4*)(smem + off)        = make_uint4(h[0],h[1],h[2],h[3]);
        *(uint4*)(smem + off + 8192) = make_uint4(l[0],l[1],l[2],l[3]);
    }

    for (int bt = 0; bt < 2; ++bt){
        float acc[2][4][4] = {};
        for (int half = 0; half < 2; ++half){
            if (bt != 0 || half != 0){
                size_t gw = (size_t)bt*32768 + (size_t)half*16384;
                cpy(sb + HG_B,         (const char*)d_WcH + gw, tid, 1024);
                cpy(sb + HG_B + 16384, (const char*)d_WcL + gw, tid, 1024);
                CP_COMMIT();
            }
            CP_WAIT(0);
            __syncthreads();
            mma_half2(sb + (uint32_t)half*16384, sb + HG_B, m0w, n0, acc);
            __syncthreads();
        }
        char* stH = smem + HG_B;
        char* stL = smem + HG_B + 16384;
        #pragma unroll
        for (int mt = 0; mt < 2; ++mt){
            int r1 = m0w + mt*16 + (lane >> 2);
            #pragma unroll
            for (int nt = 0; nt < 4; ++nt){
                int c0 = n0 + nt*8 + ((lane & 3) << 1);
                float b0 = d_bcat[bt*128 + c0], b1 = d_bcat[bt*128 + c0 + 1];
                const float* d = acc[mt][nt];
                #pragma unroll
                for (int hf = 0; hf < 2; ++hf){
                    int r = r1 + hf*8;
                    uint32_t ph, pl; pack2(d[hf*2] + b0, d[hf*2+1] + b1, ph, pl);
                    int kb = c0*2, half = kb >> 7;
                    uint32_t off = (uint32_t)half*8192 + hswz(r, kb & 127);
                    *(uint32_t*)(stH + off) = ph;
                    *(uint32_t*)(stL + off) = pl;
                }
            }
        }
        __syncthreads();
        char* gH = (char*)(bt ? d_gsH : d_hH);
        char* gL = (char*)(bt ? d_gsL : d_hL);
        #pragma unroll
        for (int half = 0; half < 2; ++half){
            size_t gb = (size_t)tile*32768 + (size_t)half*16384 + (size_t)mrow*8192;
            uint4* dH = (uint4*)(gH + gb); uint4* dL = (uint4*)(gL + gb);
            const uint4* sH = (const uint4*)(stH + half*8192);
            const uint4* sL = (const uint4*)(stL + half*8192);
            for (int i = tid; i < 512; i += 256){ dH[i] = sH[i]; dL[i] = sL[i]; }
        }
        __syncthreads();
    }
}

// ---------------------------------------------------------------------------
// k_hsT: hsT[d][q] = h[q][d]/csum[q]  (h from hi/lo images)
// ---------------------------------------------------------------------------
__global__ void k_hsT(){
    extern __shared__ float sT[];   // 128*129
    int qc = blockIdx.x, b = blockIdx.y, tid = threadIdx.x;
    size_t tileB = (size_t)(b*8 + qc)*32768;
    for (int g = tid; g < 2048; g += 256){
        int q = g >> 4, col8 = (g & 15) << 3;
        int kb = col8*2, half = kb >> 7, kb2 = kb & 127;
        size_t base = tileB + (size_t)half*16384 + hswz(q, kb2);
        uint4 uh = *(const uint4*)((const char*)d_hH + base);
        uint4 ul = *(const uint4*)((const char*)d_hL + base);
        float r = 1.0f / d_csum[b*N_ + qc*128 + q];
        const uint32_t wh[4] = {uh.x,uh.y,uh.z,uh.w};
        const uint32_t wl[4] = {ul.x,ul.y,ul.z,ul.w};
        #pragma unroll
        for (int t = 0; t < 4; ++t){
            float v0 = __bfloat162float(__ushort_as_bfloat16((unsigned short)(wh[t] & 0xffff)))
                     + __bfloat162float(__ushort_as_bfloat16((unsigned short)(wl[t] & 0xffff)));
            float v1 = __bfloat162float(__ushort_as_bfloat16((unsigned short)(wh[t] >> 16)))
                     + __bfloat162float(__ushort_as_bfloat16((unsigned short)(wl[t] >> 16)));
            sT[(col8 + 2*t)*129 + q]     = v0*r;
            sT[(col8 + 2*t + 1)*129 + q] = v1*r;
        }
    }
    __syncthreads();
    for (int g = tid; g < 2048; g += 256){
        int dd = g >> 4, q8 = (g & 15) << 3;
        int kb = q8*2, half = kb >> 7, kb2 = kb & 127;
        uint32_t h[4], l[4];
        #pragma unroll
        for (int i = 0; i < 4; ++i)
            pack2(sT[dd*129 + q8 + 2*i], sT[dd*129 + q8 + 2*i + 1], h[i], l[i]);
        size_t base = tileB + (size_t)half*16384 + hswz(dd, kb2);
        *(uint4*)((char*)d_hsTH + base) = make_uint4(h[0],h[1],h[2],h[3]);
        *(uint4*)((char*)d_hsTL + base) = make_uint4(l[0],l[1],l[2],l[3]);
    }
}

// ---------------------------------------------------------------------------
// kB stage layout: aH 0 | aL 8K | bH 16K | bL 32K (48KB); two stages = 96KB
// adj tile prefetched into stage0 B-region (16K..48K) during second MMA,
// XOR-swizzled by row for conflict-free fragment-order reads.
// ---------------------------------------------------------------------------
#define ST_AL 8192
#define ST_BH 16384
#define ST_BL 32768
#define ST_SZ 49152
#define SMEM_BYTES (2*ST_SZ + 512)

__global__ void __launch_bounds__(256, 2) kB(const float* __restrict__ adj){
    extern __shared__ char smem[];
    uint32_t sb = smem_to_u32(smem);
    int tid = threadIdx.x, lane = tid & 31, wid = tid >> 5;
    int qt = blockIdx.x, pth = blockIdx.y, b = blockIdx.z;
    int ptc = pth >> 1, mrow = pth & 1;
    int m0w = (wid >> 2)*32, n0 = (wid & 3)*32;

    size_t ga = (size_t)(b*8 + ptc)*32768 + (size_t)mrow*8192;
    size_t gb = (size_t)(b*8 + qt)*32768;

    cpy(sb,          (const char*)d_gsH + ga, tid, 512);
    cpy(sb + ST_AL,  (const char*)d_gsL + ga, tid, 512);
    cpy(sb + ST_BH,  (const char*)d_hH  + gb, tid, 1024);
    cpy(sb + ST_BL,  (const char*)d_hL  + gb, tid, 1024);
    CP_COMMIT();
    {
        uint32_t s1 = sb + ST_SZ;
        cpy(s1,         (const char*)d_gsH + ga + 16384, tid, 512);
        cpy(s1 + ST_AL, (const char*)d_gsL + ga + 16384, tid, 512);
        cpy(s1 + ST_BH, (const char*)d_hH  + gb + 16384, tid, 1024);
        cpy(s1 + ST_BL, (const char*)d_hL  + gb + 16384, tid, 1024);
        CP_COMMIT();
    }

    float acc[2][4][4] = {};
    CP_WAIT(1);
    __syncthreads();
    mma_half2(sb, sb + ST_BH, m0w, n0, acc);
    __syncthreads();                 // stage0 fully consumed

    // prefetch adj tile (64 rows x 512B) into stage0 B-region, row-swizzled
    {
        const char* adjb = (const char*)(adj + (size_t)b*N_*N_
                          + (size_t)(pth*64)*N_ + qt*128);
        for (int i = tid; i < 2048; i += 256){
            int r = i >> 5, ch = i & 31;
            asm volatile("cp.async.cg.shared.global [%0], [%1], 16;"
                :: "r"(sb + (uint32_t)ST_BH + (uint32_t)((r << 9) + ((ch ^ (r & 7)) << 4))),
                   "l"(adjb + (size_t)r*(N_*4) + ch*16));
        }
        CP_COMMIT();
    }
    CP_WAIT(1);                      // stage1 ready (adj may be in flight)
    __syncthreads();
    mma_half2(sb + ST_SZ, sb + ST_SZ + ST_BH, m0w, n0, acc);
    CP_WAIT(0);                      // adj ready

    float* scol = (float*)(smem + 2*ST_SZ);
    if (tid < 128) scol[tid] = 0.f;
    __syncthreads();

    const char* sAdj = smem + ST_BH;
    char* stH = smem;
    float cs[8] = {};
    #pragma unroll
    for (int mt = 0; mt < 2; ++mt){
        int r1 = m0w + mt*16 + (lane >> 2);
        #pragma unroll
        for (int nt = 0; nt < 4; ++nt){
            int c0 = n0 + nt*8 + ((lane & 3) << 1);
            const float* d = acc[mt][nt];
            #pragma unroll
            for (int hf = 0; hf < 2; ++hf){
                int r = r1 + hf*8;
                uint32_t aoff = (uint32_t)((r << 9)
                              + ((((c0 >> 2) ^ (r & 7)) << 4) | ((c0 & 3) << 2)));
                float2 av = *(const float2*)(sAdj + aoff);
                float e0 = d[hf*2 + 0], e1 = d[hf*2 + 1];
                float ev0 = (av.x > 0.f) ? __expf(e0) : 1.f;
                float ev1 = (av.y > 0.f) ? __expf(e1) : 1.f;
                float nv0 = (av.x > 0.f) ? ev0 : 0.f;
                float nv1 = (av.y > 0.f) ? ev1 : 0.f;
                cs[nt*2 + 0] += ev0; cs[nt*2 + 1] += ev1;
                int kb = c0*2, half = kb >> 7;
                uint32_t off = (uint32_t)half*8192 + hswz(r, kb & 127);
                *(uint32_t*)(stH + off) = packh(nv0, nv1);
            }
        }
    }
    #pragma unroll
    for (int m = 4; m < 32; m <<= 1){
        #pragma unroll
        for (int i = 0; i < 8; ++i) cs[i] += __shfl_xor_sync(0xffffffffu, cs[i], m);
    }
    if (lane < 4){
        #pragma unroll
        for (int nt = 0; nt < 4; ++nt){
            atomicAdd(&scol[n0 + nt*8 + 2*lane],     cs[nt*2]);
            atomicAdd(&scol[n0 + nt*8 + 2*lane + 1], cs[nt*2 + 1]);
        }
    }
    __syncthreads();
    if (tid < 128) atomicAdd(&d_csum[b*N_ + qt*128 + tid], scol[tid]);

    size_t tnum = (size_t)(b*64 + ptc*8 + qt)*32768 + (size_t)mrow*8192;
    #pragma unroll
    for (int half = 0; half < 2; ++half){
        uint4* gH = (uint4*)((char*)d_numH + tnum + (size_t)half*16384);
        const uint4* sH = (const uint4*)(stH + half*8192);
        for (int i = tid; i < 512; i += 256) gH[i] = sH[i];
    }
}

// ---------------------------------------------------------------------------
// kC stage layout: aH 0 | bH 8K | bL 24K (40KB); two stages = 80KB
// ---------------------------------------------------------------------------
#define C_BH 8192
#define C_BL 24576
#define C_SZ 40960
#define C_SMEM (2*C_SZ)

__global__ void __launch_bounds__(256, 2) kC(const float* __restrict__ x,
        const float* __restrict__ wiu, const float* __restrict__ wix,
        const float* __restrict__ wfu, const float* __restrict__ wfx,
        const float* __restrict__ wou, const float* __restrict__ wox,
        float* __restrict__ out){
    extern __shared__ char smem[];
    uint32_t sb = smem_to_u32(smem);
    int tid = threadIdx.x, lane = tid & 31, wid = tid >> 5;
    int pt = blockIdx.x, mh = blockIdx.y, b = blockIdx.z;
    int m0w = (wid >> 2)*32, n0 = (wid & 3)*32, wn = wid & 3;

    {
        size_t ta = (size_t)(b*64 + pt*8)*32768 + (size_t)mh*8192;
        size_t tb = (size_t)(b*8)*32768;
        cpy(sb,        (const char*)d_numH + ta, tid, 512);
        cpy(sb + C_BH, (const char*)d_hsTH + tb, tid, 1024);
        cpy(sb + C_BL, (const char*)d_hsTL + tb, tid, 1024);
        CP_COMMIT();
    }

    float acc[2][4][4] = {};
    for (int t = 0; t < 16; ++t){
        if (t < 15){
            int tn = t + 1, qc = tn >> 1, kh = tn & 1;
            uint32_t s = sb + (uint32_t)((tn & 1) ? C_SZ : 0);
            size_t ta = (size_t)(b*64 + pt*8 + qc)*32768 + (size_t)kh*16384 + (size_t)mh*8192;
            size_t tb = (size_t)(b*8 + qc)*32768 + (size_t)kh*16384;
            cpy(s,        (const char*)d_numH + ta, tid, 512);
            cpy(s + C_BH, (const char*)d_hsTH + tb, tid, 1024);
            cpy(s + C_BL, (const char*)d_hsTL + tb, tid, 1024);
            CP_COMMIT();
            CP_WAIT(1);
        } else {
            CP_WAIT(0);
        }
        __syncthreads();
        uint32_t st = sb + (uint32_t)((t & 1) ? C_SZ : 0);
        mma_half2t(st, st + C_BH, m0w, n0, acc);
        __syncthreads();
    }

    float* sx    = (float*)smem;                 // [64][132]
    float* sw    = (float*)(smem + 33792);       // [6][128]
    float* sPart = (float*)(smem + 36864);       // [4 wn][3][64]
    float* sGate = (float*)(smem + 39936);       // [3][64]
    const float* xb = x + ((size_t)b*N_ + pt*128 + mh*64)*D_;
    for (int g = tid; g < 2048; g += 256){
        int row = g >> 5, c4 = (g & 31) << 2;
        float4 v = *(const float4*)&xb[(size_t)row*D_ + c4];
        float* p = &sx[row*132 + c4];
        p[0]=v.x; p[1]=v.y; p[2]=v.z; p[3]=v.w;
    }
    if (tid < 128){
        sw[tid]       = wiu[tid]; sw[128 + tid] = wfu[tid]; sw[256 + tid] = wou[tid];
        sw[384 + tid] = wix[tid]; sw[512 + tid] = wfx[tid]; sw[640 + tid] = wox[tid];
    }
    __syncthreads();

    float pi[4] = {}, pf[4] = {}, po[4] = {};
    #pragma unroll
    for (int mt = 0; mt < 2; ++mt){
        #pragma unroll
        for (int nt = 0; nt < 4; ++nt){
            int c0 = n0 + nt*8 + ((lane & 3) << 1);
            float wi0 = sw[c0], wi1 = sw[c0+1];
            float wf0 = sw[128+c0], wf1 = sw[129+c0];
            float wo0 = sw[256+c0], wo1 = sw[257+c0];
            const float* d = acc[mt][nt];
            #pragma unroll
            for (int hf = 0; hf < 2; ++hf){
                float h0 = fmaxf(d[hf*2], 0.f), h1 = fmaxf(d[hf*2+1], 0.f);
                pi[mt*2+hf] += h0*wi0 + h1*wi1;
                pf[mt*2+hf] += h0*wf0 + h1*wf1;
                po[mt*2+hf] += h0*wo0 + h1*wo1;
            }
        }
    }
    #pragma unroll
    for (int m = 1; m < 4; m <<= 1){
        #pragma unroll
        for (int i = 0; i < 4; ++i){
            pi[i] += __shfl_xor_sync(0xffffffffu, pi[i], m);
            pf[i] += __shfl_xor_sync(0xffffffffu, pf[i], m);
            po[i] += __shfl_xor_sync(0xffffffffu, po[i], m);
        }
    }
    if ((lane & 3) == 0){
        #pragma unroll
        for (int mt = 0; mt < 2; ++mt)
        #pragma unroll
        for (int hf = 0; hf < 2; ++hf){
            int rl = m0w + mt*16 + (lane >> 2) + hf*8;
            sPart[(wn*3 + 0)*64 + rl] = pi[mt*2+hf];
            sPart[(wn*3 + 1)*64 + rl] = pf[mt*2+hf];
            sPart[(wn*3 + 2)*64 + rl] = po[mt*2+hf];
        }
    }
    __syncthreads();
    if (tid < 64){
        int r = tid;
        float si = 0.f, sf = 0.f, so = 0.f;
        #pragma unroll
        for (int w = 0; w < 4; ++w){
            si += sPart[(w*3 + 0)*64 + r];
            sf += sPart[(w*3 + 1)*64 + r];
            so += sPart[(w*3 + 2)*64 + r];
        }
        const float* srow = &sx[r*132];
        #pragma unroll 8
        for (int c = 0; c < 128; ++c){
            float xv = srow[c];
            si = fmaf(xv, sw[384 + c], si);
            sf = fmaf(xv, sw[512 + c], sf);
            so = fmaf(xv, sw[640 + c], so);
        }
        sGate[r]        = fast_sigmoid(si);
        sGate[64 + r]   = fast_sigmoid(sf);
        sGate[128 + r]  = fast_sigmoid(so);
    }
    __syncthreads();

    float* outb = out + ((size_t)b*N_ + pt*128 + mh*64)*D_;
    #pragma unroll
    for (int mt = 0; mt < 2; ++mt){
        #pragma unroll
        for (int nt = 0; nt < 4; ++nt){
            int c0 = n0 + nt*8 + ((lane & 3) << 1);
            const float* d = acc[mt][nt];
            #pragma unroll
            for (int hf = 0; hf < 2; ++hf){
                int rl = m0w + mt*16 + (lane >> 2) + hf*8;
                float ic = sGate[rl], fc = sGate[64 + rl], oc = sGate[128 + rl];
                float x0 = sx[rl*132 + c0], x1 = sx[rl*132 + c0 + 1];
                float h0 = fmaxf(d[hf*2], 0.f), h1 = fmaxf(d[hf*2+1], 0.f);
                float2 o;
                o.x = oc * fast_tanh(fmaf(ic, h0, fc*x0));
                o.y = oc * fast_tanh(fmaf(ic, h1, fc*x1));
                *(float2*)&outb[(size_t)rl*D_ + c0] = o;
            }
        }
    }
}

// ---------------------------------------------------------------------------
extern "C" void kernel_launch(void* const* d_in, const int* in_sizes, int n_in,
                              void* d_out, int out_size){
    const float* x   = (const float*)d_in[0];
    const float* adj = (const float*)d_in[1];
    const float* Ww  = (const float*)d_in[2];
    const float* Wb  = (const float*)d_in[3];
    const float* A   = (const float*)d_in[4];
    const float* wiu = (const float*)d_in[5];
    const float* wix = (const float*)d_in[6];
    const float* wfu = (const float*)d_in[7];
    const float* wfx = (const float*)d_in[8];
    const float* wou = (const float*)d_in[9];
    const float* wox = (const float*)d_in[10];
    float* out = (float*)d_out;

    cudaFuncSetAttribute(kB, cudaFuncAttributeMaxDynamicSharedMemorySize, SMEM_BYTES);
    cudaFuncSetAttribute(kC, cudaFuncAttributeMaxDynamicSharedMemorySize, C_SMEM);
    cudaFuncSetAttribute(k_hg_mma, cudaFuncAttributeMaxDynamicSharedMemorySize, HG_SMEM);
    cudaFuncSetAttribute(k_hsT, cudaFuncAttributeMaxDynamicSharedMemorySize, 128*129*4);

    k_prep<<<64, 256>>>(Ww, A);
    k_prep2<<<65, 256>>>(Ww, Wb);
    k_wsplit<<<16, 256>>>();
    k_hg_mma<<<256, 256, HG_SMEM>>>(x);
    kB<<<dim3(8, 16, B_), 256, SMEM_BYTES>>>(adj);
    k_hsT<<<dim3(8, B_), 256, 128*129*4>>>();
    kC<<<dim3(8, 2, B_), 256, C_SMEM>>>(x, wiu, wix, wfu, wfx, wou, wox, out);
}